// round 6
// baseline (speedup 1.0000x reference)
#include <cuda_runtime.h>
#include <cuda_bf16.h>
#include <cstdint>
#include <cstddef>

#define N_NODES 50000
#define N_EDGES 600000
#define IN_DIM  16
#define HIDDEN  128
#define OUT_DIM 4

typedef __nv_bfloat16 bf16;

// ---------------- device scratch (static: no allocs allowed) ----------------
__device__ int   g_deg[N_NODES];
__device__ int   g_off[N_NODES + 1];
__device__ int   g_pos[N_NODES];
__device__ int   g_csr[N_EDGES];
__device__ int   g_is32;
__device__ int   g_bsum[80];

__device__ float g_agg[(size_t)N_NODES * IN_DIM];      // layer1 agg (f32)
__device__ float g_hf [(size_t)N_NODES * HIDDEN];      // layer3 f32 out (head input)
// bf16 hi/lo splits of activations
__device__ bf16  g_h1h[(size_t)N_NODES * HIDDEN];
__device__ bf16  g_h1l[(size_t)N_NODES * HIDDEN];
__device__ bf16  g_h2h[(size_t)N_NODES * HIDDEN];
__device__ bf16  g_h2l[(size_t)N_NODES * HIDDEN];
// W splits: order Wl2, Wr2, Wl3, Wr3
__device__ bf16  g_Wh[4][HIDDEN * HIDDEN];
__device__ bf16  g_Wl[4][HIDDEN * HIDDEN];

// ---------------- helpers ----------------
__device__ __forceinline__ void bsplit(float x, bf16& h, bf16& l) {
    h = __float2bfloat16_rn(x);
    l = __float2bfloat16_rn(x - __bfloat162float(h));
}

__device__ __forceinline__ void mma_bf16(float c[4], const uint32_t a[4],
                                         uint32_t b0, uint32_t b1) {
    asm volatile(
        "mma.sync.aligned.m16n8k16.row.col.f32.bf16.bf16.f32 "
        "{%0,%1,%2,%3}, {%4,%5,%6,%7}, {%8,%9}, {%0,%1,%2,%3};"
        : "+f"(c[0]), "+f"(c[1]), "+f"(c[2]), "+f"(c[3])
        : "r"(a[0]), "r"(a[1]), "r"(a[2]), "r"(a[3]), "r"(b0), "r"(b1));
}

__device__ __forceinline__ int load_idx(const void* ei, long long pos, int is32) {
    if (is32) return ((const int*)ei)[pos];
    return (int)(((const long long*)ei)[pos]);
}

// ---------------- prep: detect dtype + zero deg + split W ----------------
__global__ void k_prep(const void* ei,
                       const float* __restrict__ Wl2, const float* __restrict__ Wr2,
                       const float* __restrict__ Wl3, const float* __restrict__ Wr3) {
    int idx = blockIdx.x * 1024 + threadIdx.x;   // 64 blocks x 1024 = 65536
    // W split
    {
        int w = idx >> 14;
        int e = idx & 16383;
        const float* src = (w == 0) ? Wl2 : (w == 1) ? Wr2 : (w == 2) ? Wl3 : Wr3;
        float v = src[e];
        bf16 h, l;
        bsplit(v, h, l);
        g_Wh[w][e] = h;
        g_Wl[w][e] = l;
    }
    if (idx < N_NODES) g_deg[idx] = 0;
    // dtype detect (block 0 only)
    if (blockIdx.x == 0) {
        __shared__ unsigned s_m[2];
        int t = threadIdx.x;
        if (t < 64) {
            long long v = ((const long long*)ei)[t];
            int bad = (v < 0 || v >= N_NODES) ? 1 : 0;
            unsigned m0 = __ballot_sync(0xffffffffu, bad);
            s_m[t >> 5] = m0;
        }
        __syncthreads();
        if (t == 0) g_is32 = (s_m[0] | s_m[1]) ? 1 : 0;
    }
}

// ---------------- CSR build (4 edges/thread for MLP) ----------------
__global__ void k_count(const void* ei) {
    int base = blockIdx.x * 1024 + threadIdx.x;
    int is32 = g_is32;
    int d[4];
    #pragma unroll
    for (int k = 0; k < 4; k++) {
        int e = base + k * 256;
        d[k] = (e < N_EDGES) ? load_idx(ei, (long long)N_EDGES + e, is32) : -1;
    }
    #pragma unroll
    for (int k = 0; k < 4; k++)
        if (d[k] >= 0) atomicAdd(&g_deg[d[k]], 1);
}

// pass 1: per-block exclusive scan + block sums
__global__ void k_scan1() {
    __shared__ int warp_sums[32];
    int tid = threadIdx.x;  // 1024
    int i = blockIdx.x * 1024 + tid;
    int v = (i < N_NODES) ? g_deg[i] : 0;
    int x = v;
    #pragma unroll
    for (int d = 1; d < 32; d <<= 1) {
        int y = __shfl_up_sync(0xffffffffu, x, d);
        if ((tid & 31) >= d) x += y;
    }
    if ((tid & 31) == 31) warp_sums[tid >> 5] = x;
    __syncthreads();
    if (tid < 32) {
        int w = warp_sums[tid];
        #pragma unroll
        for (int d = 1; d < 32; d <<= 1) {
            int y = __shfl_up_sync(0xffffffffu, w, d);
            if (tid >= d) w += y;
        }
        warp_sums[tid] = w;
    }
    __syncthreads();
    int incl = x + ((tid >= 32) ? warp_sums[(tid >> 5) - 1] : 0);
    if (i < N_NODES) g_off[i] = incl - v;
    if (tid == 0) g_bsum[blockIdx.x] = warp_sums[31];
}

__global__ void k_scan2(int nblk) {
    int t = threadIdx.x;  // 32
    int v0 = (t < nblk) ? g_bsum[t] : 0;
    int v1 = (32 + t < nblk) ? g_bsum[32 + t] : 0;
    int x0 = v0, x1 = v1;
    #pragma unroll
    for (int d = 1; d < 32; d <<= 1) {
        int y0 = __shfl_up_sync(0xffffffffu, x0, d);
        int y1 = __shfl_up_sync(0xffffffffu, x1, d);
        if (t >= d) { x0 += y0; x1 += y1; }
    }
    int tot0 = __shfl_sync(0xffffffffu, x0, 31);
    int tot1 = __shfl_sync(0xffffffffu, x1, 31);
    g_bsum[t] = x0 - v0;
    g_bsum[32 + t] = x1 - v1 + tot0;
    if (t == 0) g_off[N_NODES] = tot0 + tot1;
}

__global__ void k_scan3() {
    int i = blockIdx.x * 1024 + threadIdx.x;
    if (i >= N_NODES) return;
    int off = g_off[i] + g_bsum[blockIdx.x];
    g_off[i] = off;
    g_pos[i] = off;
}

__global__ void k_fill(const void* ei) {
    int base = blockIdx.x * 1024 + threadIdx.x;
    int is32 = g_is32;
    int s[4], d[4];
    #pragma unroll
    for (int k = 0; k < 4; k++) {
        int e = base + k * 256;
        if (e < N_EDGES) {
            s[k] = load_idx(ei, e, is32);
            d[k] = load_idx(ei, (long long)N_EDGES + e, is32);
        } else d[k] = -1;
    }
    #pragma unroll
    for (int k = 0; k < 4; k++) {
        if (d[k] >= 0) {
            int p = atomicAdd(&g_pos[d[k]], 1);
            g_csr[p] = s[k];
        }
    }
}

// ---------------- layer-1 aggregation (F=16, f32) ----------------
__global__ void k_agg16(const float* __restrict__ x) {
    int warp = (blockIdx.x * blockDim.x + threadIdx.x) >> 5;
    int lane = threadIdx.x & 31;
    if (warp >= N_NODES) return;
    int beg = g_off[warp], end = g_off[warp + 1];
    float acc = 0.f;
    for (int i = beg; i < end; i++) {
        int s = g_csr[i];
        if (lane < 16) acc += x[(size_t)s * IN_DIM + lane];
    }
    float inv = 1.0f / fmaxf((float)(end - beg), 1.0f);
    if (lane < 16) g_agg[(size_t)warp * IN_DIM + lane] = acc * inv;
}

// ---------------- layer-1 FFMA GEMM (K=16 per segment), hi/lo out ----------
__global__ __launch_bounds__(256)
void k_sage_gemm(const float* __restrict__ A1, const float* __restrict__ A2,
                 const float* __restrict__ W1, const float* __restrict__ W2,
                 const float* __restrict__ bias,
                 bf16* __restrict__ out_hi, bf16* __restrict__ out_lo,
                 int K)
{
    __shared__ float As[16][128];
    __shared__ float Ws[16][128];
    int tid = threadIdx.x;
    int tx = tid & 15;
    int ty = tid >> 4;
    int row0 = blockIdx.x * 128;

    float c[8][8];
    #pragma unroll
    for (int i = 0; i < 8; i++)
        #pragma unroll
        for (int j = 0; j < 8; j++) c[i][j] = 0.f;

    #pragma unroll
    for (int seg = 0; seg < 2; seg++) {
        const float* A = seg ? A2 : A1;
        const float* W = seg ? W2 : W1;
        for (int kk = 0; kk < K; kk += 16) {
            #pragma unroll
            for (int t = 0; t < 2; t++) {
                int idx = tid + t * 256;
                int m  = idx >> 2;
                int kq = idx & 3;
                int gm = row0 + m;
                float4 v = make_float4(0.f, 0.f, 0.f, 0.f);
                if (gm < N_NODES)
                    v = *(const float4*)(A + (size_t)gm * K + kk + kq * 4);
                As[kq * 4 + 0][m] = v.x; As[kq * 4 + 1][m] = v.y;
                As[kq * 4 + 2][m] = v.z; As[kq * 4 + 3][m] = v.w;
                float4 w = *(const float4*)(W + (size_t)m * K + kk + kq * 4);
                Ws[kq * 4 + 0][m] = w.x; Ws[kq * 4 + 1][m] = w.y;
                Ws[kq * 4 + 2][m] = w.z; Ws[kq * 4 + 3][m] = w.w;
            }
            __syncthreads();
            #pragma unroll
            for (int k = 0; k < 16; k++) {
                float a[8], w[8];
                *(float4*)&a[0] = *(const float4*)&As[k][ty * 8];
                *(float4*)&a[4] = *(const float4*)&As[k][ty * 8 + 4];
                *(float4*)&w[0] = *(const float4*)&Ws[k][tx * 8];
                *(float4*)&w[4] = *(const float4*)&Ws[k][tx * 8 + 4];
                #pragma unroll
                for (int i = 0; i < 8; i++)
                    #pragma unroll
                    for (int j = 0; j < 8; j++)
                        c[i][j] += a[i] * w[j];
            }
            __syncthreads();
        }
    }

    #pragma unroll
    for (int i = 0; i < 8; i++) {
        int gm = row0 + ty * 8 + i;
        if (gm >= N_NODES) continue;
        #pragma unroll
        for (int j = 0; j < 8; j += 4) {
            int gn = tx * 8 + j;
            bf16 vh[4], vl[4];
            #pragma unroll
            for (int q = 0; q < 4; q++) {
                float v = fmaxf(c[i][j + q] + bias[gn + q], 0.f);
                bsplit(v, vh[q], vl[q]);
            }
            *(uint2*)(out_hi + (size_t)gm * 128 + gn) = *(const uint2*)vh;
            *(uint2*)(out_lo + (size_t)gm * 128 + gn) = *(const uint2*)vl;
        }
    }
}

// ---------------- fused agg + split-HMMA GEMM (layers 2+3) ----------------
// Phase 1: per-CTA mean-aggregate 128 node rows from H (hi/lo) into smem.
// Phase 2: out = relu([Agg|H](M,256) @ [B1|B2](128,256)^T + bias)
#define SMA 136   // A1 smem stride (halves)
#define SKB 40    // chunk-tile stride (halves)

template<int AS>
__device__ __forceinline__ void gemm_chunk(
    const bf16* __restrict__ Ah, const bf16* __restrict__ Al,
    const bf16 (*__restrict__ Wh)[SKB], const bf16 (*__restrict__ Wl)[SKB],
    float c[2][8][4], int warp_m, int warp_n, int gp, int tg, int kbase)
{
    #pragma unroll
    for (int ks = 0; ks < 2; ks++) {
        int ka = kbase + ks * 16 + 2 * tg;
        int kw = ks * 16 + 2 * tg;
        uint32_t ah[2][4], al[2][4];
        #pragma unroll
        for (int mt = 0; mt < 2; mt++) {
            int r = warp_m * 32 + mt * 16 + gp;
            const bf16* p0 = Ah + r * AS + ka;
            const bf16* p1 = Ah + (r + 8) * AS + ka;
            ah[mt][0] = *(const uint32_t*)p0;
            ah[mt][1] = *(const uint32_t*)p1;
            ah[mt][2] = *(const uint32_t*)(p0 + 8);
            ah[mt][3] = *(const uint32_t*)(p1 + 8);
            const bf16* q0 = Al + r * AS + ka;
            const bf16* q1 = Al + (r + 8) * AS + ka;
            al[mt][0] = *(const uint32_t*)q0;
            al[mt][1] = *(const uint32_t*)q1;
            al[mt][2] = *(const uint32_t*)(q0 + 8);
            al[mt][3] = *(const uint32_t*)(q1 + 8);
        }
        #pragma unroll
        for (int nt = 0; nt < 8; nt++) {
            int n = warp_n * 64 + nt * 8 + gp;
            uint32_t bh0 = *(const uint32_t*)&Wh[n][kw];
            uint32_t bh1 = *(const uint32_t*)&Wh[n][kw + 8];
            uint32_t bl0 = *(const uint32_t*)&Wl[n][kw];
            uint32_t bl1 = *(const uint32_t*)&Wl[n][kw + 8];
            #pragma unroll
            for (int mt = 0; mt < 2; mt++) {
                mma_bf16(c[mt][nt], ah[mt], bh0, bh1);
                mma_bf16(c[mt][nt], ah[mt], bl0, bl1);
                mma_bf16(c[mt][nt], al[mt], bh0, bh1);
            }
        }
    }
}

__global__ __launch_bounds__(256, 2)
void k_fused(const bf16* __restrict__ Hh, const bf16* __restrict__ Hl,
             const bf16* __restrict__ B1h, const bf16* __restrict__ B1l,
             const bf16* __restrict__ B2h, const bf16* __restrict__ B2l,
             const float* __restrict__ bias,
             float* __restrict__ outf,
             bf16* __restrict__ outh, bf16* __restrict__ outl,
             int flags)   // 1 = write f32, 2 = write hi/lo
{
    extern __shared__ char sm[];
    bf16 (*sA1h)[SMA] = (bf16(*)[SMA])(sm);
    bf16 (*sA1l)[SMA] = (bf16(*)[SMA])(sm + 34816);
    bf16 (*sA2h)[SKB] = (bf16(*)[SKB])(sm + 69632);
    bf16 (*sA2l)[SKB] = (bf16(*)[SKB])(sm + 79872);
    bf16 (*sWh)[SKB]  = (bf16(*)[SKB])(sm + 90112);
    bf16 (*sWl)[SKB]  = (bf16(*)[SKB])(sm + 100352);

    int tid = threadIdx.x;
    int wid = tid >> 5;
    int lane = tid & 31;
    int tg = lane & 3;
    int gp = lane >> 2;
    int warp_m = wid & 3;
    int warp_n = wid >> 2;
    int row0 = blockIdx.x * 128;

    // ---- phase 1: aggregate 128 rows into sA1 (bf16 hi/lo) ----
    for (int i = 0; i < 16; i++) {
        int m = wid * 16 + i;
        int node = row0 + m;
        if (node < N_NODES) {
            int beg = g_off[node], end = g_off[node + 1];
            float a0 = 0.f, a1 = 0.f, a2 = 0.f, a3 = 0.f;
            int j = beg;
            for (; j + 1 < end; j += 2) {
                int s0 = g_csr[j], s1 = g_csr[j + 1];
                uint2 u0h = *(const uint2*)(Hh + ((size_t)s0 << 7) + (lane << 2));
                uint2 u0l = *(const uint2*)(Hl + ((size_t)s0 << 7) + (lane << 2));
                uint2 u1h = *(const uint2*)(Hh + ((size_t)s1 << 7) + (lane << 2));
                uint2 u1l = *(const uint2*)(Hl + ((size_t)s1 << 7) + (lane << 2));
                float2 f;
                f = __bfloat1622float2(*(__nv_bfloat162*)&u0h.x); a0 += f.x; a1 += f.y;
                f = __bfloat1622float2(*(__nv_bfloat162*)&u0h.y); a2 += f.x; a3 += f.y;
                f = __bfloat1622float2(*(__nv_bfloat162*)&u0l.x); a0 += f.x; a1 += f.y;
                f = __bfloat1622float2(*(__nv_bfloat162*)&u0l.y); a2 += f.x; a3 += f.y;
                f = __bfloat1622float2(*(__nv_bfloat162*)&u1h.x); a0 += f.x; a1 += f.y;
                f = __bfloat1622float2(*(__nv_bfloat162*)&u1h.y); a2 += f.x; a3 += f.y;
                f = __bfloat1622float2(*(__nv_bfloat162*)&u1l.x); a0 += f.x; a1 += f.y;
                f = __bfloat1622float2(*(__nv_bfloat162*)&u1l.y); a2 += f.x; a3 += f.y;
            }
            if (j < end) {
                int s0 = g_csr[j];
                uint2 u0h = *(const uint2*)(Hh + ((size_t)s0 << 7) + (lane << 2));
                uint2 u0l = *(const uint2*)(Hl + ((size_t)s0 << 7) + (lane << 2));
                float2 f;
                f = __bfloat1622float2(*(__nv_bfloat162*)&u0h.x); a0 += f.x; a1 += f.y;
                f = __bfloat1622float2(*(__nv_bfloat162*)&u0h.y); a2 += f.x; a3 += f.y;
                f = __bfloat1622float2(*(__nv_bfloat162*)&u0l.x); a0 += f.x; a1 += f.y;
                f = __bfloat1622float2(*(__nv_bfloat162*)&u0l.y); a2 += f.x; a3 += f.y;
            }
            float inv = 1.0f / fmaxf((float)(end - beg), 1.0f);
            bf16 vh[4], vl[4];
            bsplit(a0 * inv, vh[0], vl[0]);
            bsplit(a1 * inv, vh[1], vl[1]);
            bsplit(a2 * inv, vh[2], vl[2]);
            bsplit(a3 * inv, vh[3], vl[3]);
            *(uint2*)&sA1h[m][lane * 4] = *(const uint2*)vh;
            *(uint2*)&sA1l[m][lane * 4] = *(const uint2*)vl;
        }
    }
    __syncthreads();

    // ---- phase 2: GEMM over 8 K-chunks ----
    float c[2][8][4];
    #pragma unroll
    for (int mt = 0; mt < 2; mt++)
        #pragma unroll
        for (int nt = 0; nt < 8; nt++)
            #pragma unroll
            for (int q = 0; q < 4; q++) c[mt][nt][q] = 0.f;

    for (int ch = 0; ch < 8; ch++) {
        if (ch) __syncthreads();
        int seg = ch >> 2;
        int k0 = (ch & 3) * 32;
        const bf16* Wsh = seg ? B2h : B1h;
        const bf16* Wsl = seg ? B2l : B1l;
        #pragma unroll
        for (int t = 0; t < 2; t++) {
            int idx = tid + t * 256;
            int m = idx >> 2, q = idx & 3;
            *(float4*)&sWh[m][q * 8] = *(const float4*)(Wsh + (size_t)m * 128 + k0 + q * 8);
            *(float4*)&sWl[m][q * 8] = *(const float4*)(Wsl + (size_t)m * 128 + k0 + q * 8);
            if (seg) {
                int gm = row0 + m;
                float4 va = make_float4(0.f, 0.f, 0.f, 0.f), vb = va;
                if (gm < N_NODES) {
                    va = *(const float4*)(Hh + (size_t)gm * 128 + k0 + q * 8);
                    vb = *(const float4*)(Hl + (size_t)gm * 128 + k0 + q * 8);
                }
                *(float4*)&sA2h[m][q * 8] = va;
                *(float4*)&sA2l[m][q * 8] = vb;
            }
        }
        __syncthreads();
        if (seg == 0)
            gemm_chunk<SMA>(&sA1h[0][0], &sA1l[0][0], sWh, sWl, c, warp_m, warp_n, gp, tg, k0);
        else
            gemm_chunk<SKB>(&sA2h[0][0], &sA2l[0][0], sWh, sWl, c, warp_m, warp_n, gp, tg, 0);
    }

    // ---- epilogue ----
    #pragma unroll
    for (int mt = 0; mt < 2; mt++) {
        int row = row0 + warp_m * 32 + mt * 16 + gp;
        #pragma unroll
        for (int nt = 0; nt < 8; nt++) {
            int col = warp_n * 64 + nt * 8 + 2 * tg;
            float b0 = bias[col], b1 = bias[col + 1];
            #pragma unroll
            for (int half = 0; half < 2; half++) {
                int r = row + half * 8;
                if (r < N_NODES) {
                    float v0 = fmaxf(c[mt][nt][half * 2 + 0] + b0, 0.f);
                    float v1 = fmaxf(c[mt][nt][half * 2 + 1] + b1, 0.f);
                    if (flags & 1)
                        *(float2*)(outf + (size_t)r * 128 + col) = make_float2(v0, v1);
                    if (flags & 2) {
                        bf16 h0, l0, h1, l1;
                        bsplit(v0, h0, l0); bsplit(v1, h1, l1);
                        bf16 hh[2] = {h0, h1}, ll[2] = {l0, l1};
                        *(uint32_t*)(outh + (size_t)r * 128 + col) = *(const uint32_t*)hh;
                        *(uint32_t*)(outl + (size_t)r * 128 + col) = *(const uint32_t*)ll;
                    }
                }
            }
        }
    }
}

// ---------------- head ----------------
__global__ void k_head(const float* __restrict__ h, const float* __restrict__ Wh,
                       const float* __restrict__ bh, float* __restrict__ out)
{
    int warp = (blockIdx.x * blockDim.x + threadIdx.x) >> 5;
    int lane = threadIdx.x & 31;
    if (warp >= N_NODES) return;
    float4 hv = *(const float4*)(h + ((size_t)warp << 7) + (lane << 2));
    float p[4];
    #pragma unroll
    for (int o = 0; o < 4; o++) {
        float4 w = *(const float4*)(Wh + o * 128 + (lane << 2));
        float s = hv.x * w.x + hv.y * w.y + hv.z * w.z + hv.w * w.w;
        #pragma unroll
        for (int d = 16; d > 0; d >>= 1) s += __shfl_xor_sync(0xffffffffu, s, d);
        p[o] = s;
    }
    if (lane == 0) {
        float4 v = make_float4(p[0] + bh[0], p[1] + bh[1], p[2] + bh[2], p[3] + bh[3]);
        *(float4*)(out + (size_t)warp * 4) = v;
    }
}

// ---------------- launch ----------------
extern "C" void kernel_launch(void* const* d_in, const int* in_sizes, int n_in,
                              void* d_out, int out_size)
{
    const float* x   = (const float*)d_in[0];
    const void*  ei  = d_in[1];
    const float* Wl1 = (const float*)d_in[2];
    const float* Wr1 = (const float*)d_in[3];
    const float* b1  = (const float*)d_in[4];
    const float* Wl2 = (const float*)d_in[5];
    const float* Wr2 = (const float*)d_in[6];
    const float* b2  = (const float*)d_in[7];
    const float* Wl3 = (const float*)d_in[8];
    const float* Wr3 = (const float*)d_in[9];
    const float* b3  = (const float*)d_in[10];
    const float* Wh  = (const float*)d_in[11];
    const float* bh  = (const float*)d_in[12];
    float* out = (float*)d_out;

    float *p_agg, *p_hf;
    bf16 *p_h1h, *p_h1l, *p_h2h, *p_h2l, *p_Whs, *p_Wls;
    cudaGetSymbolAddress((void**)&p_agg,  g_agg);
    cudaGetSymbolAddress((void**)&p_hf,   g_hf);
    cudaGetSymbolAddress((void**)&p_h1h,  g_h1h);
    cudaGetSymbolAddress((void**)&p_h1l,  g_h1l);
    cudaGetSymbolAddress((void**)&p_h2h,  g_h2h);
    cudaGetSymbolAddress((void**)&p_h2l,  g_h2l);
    cudaGetSymbolAddress((void**)&p_Whs,  g_Wh);
    cudaGetSymbolAddress((void**)&p_Wls,  g_Wl);

    const int WB = (N_NODES + 7) / 8;
    const int GB = (N_NODES + 127) / 128;        // 391
    const int SB = (N_NODES + 1023) / 1024;      // 49
    const int CB = (N_EDGES + 1023) / 1024;      // 586
    const int FSM = 110592;

    // idempotent; no static guard (harness forbids call-count state)
    cudaFuncSetAttribute(k_fused, cudaFuncAttributeMaxDynamicSharedMemorySize, FSM);

    // graph structure + W split
    k_prep<<<64, 1024>>>(ei, Wl2, Wr2, Wl3, Wr3);
    k_count<<<CB, 256>>>(ei);
    k_scan1<<<SB, 1024>>>();
    k_scan2<<<1, 32>>>(SB);
    k_scan3<<<SB, 1024>>>();
    k_fill<<<CB, 256>>>(ei);

    const int HH = HIDDEN * HIDDEN;

    // layer 1 (FFMA, K=16) -> h1 hi/lo
    k_agg16<<<WB, 256>>>(x);
    k_sage_gemm<<<GB, 256>>>(p_agg, x, Wl1, Wr1, b1, p_h1h, p_h1l, IN_DIM);

    // layer 2 (fused agg + HMMA) -> h2 hi/lo
    k_fused<<<GB, 256, FSM>>>(p_h1h, p_h1l,
                              p_Whs + 0 * HH, p_Wls + 0 * HH,
                              p_Whs + 1 * HH, p_Wls + 1 * HH,
                              b2, nullptr, p_h2h, p_h2l, 2);

    // layer 3 (fused agg + HMMA) -> f32 for head
    k_fused<<<GB, 256, FSM>>>(p_h2h, p_h2l,
                              p_Whs + 2 * HH, p_Wls + 2 * HH,
                              p_Whs + 3 * HH, p_Wls + 3 * HH,
                              b3, p_hf, nullptr, nullptr, 1);

    // head
    k_head<<<WB, 256>>>(p_hf, Wh, bh, out);
}

// round 7
// speedup vs baseline: 2.1140x; 2.1140x over previous
#include <cuda_runtime.h>
#include <cuda_bf16.h>
#include <cstdint>
#include <cstddef>

#define N_NODES 50000
#define N_EDGES 600000
#define IN_DIM  16
#define HIDDEN  128
#define OUT_DIM 4

typedef __nv_bfloat16 bf16;

// ---------------- device scratch (static: no allocs allowed) ----------------
__device__ int   g_deg[N_NODES];
__device__ int   g_off[N_NODES + 1];
__device__ int   g_pos[N_NODES];
__device__ int   g_csr[N_EDGES];
__device__ int   g_is32;
__device__ int   g_bsum[80];

__device__ float g_agg[(size_t)N_NODES * IN_DIM];      // layer1 agg (f32)
__device__ float g_hf [(size_t)N_NODES * HIDDEN];      // layer3 f32 out (head input)
// bf16 hi/lo splits
__device__ bf16  g_aggh[(size_t)N_NODES * HIDDEN];
__device__ bf16  g_aggl[(size_t)N_NODES * HIDDEN];
__device__ bf16  g_h1h[(size_t)N_NODES * HIDDEN];
__device__ bf16  g_h1l[(size_t)N_NODES * HIDDEN];
__device__ bf16  g_h2h[(size_t)N_NODES * HIDDEN];
__device__ bf16  g_h2l[(size_t)N_NODES * HIDDEN];
// W splits: order Wl2, Wr2, Wl3, Wr3
__device__ bf16  g_Wh[4][HIDDEN * HIDDEN];
__device__ bf16  g_Wl[4][HIDDEN * HIDDEN];

// ---------------- helpers ----------------
__device__ __forceinline__ void bsplit(float x, bf16& h, bf16& l) {
    h = __float2bfloat16_rn(x);
    l = __float2bfloat16_rn(x - __bfloat162float(h));
}

__device__ __forceinline__ void mma_bf16(float c[4], const uint32_t a[4],
                                         uint32_t b0, uint32_t b1) {
    asm volatile(
        "mma.sync.aligned.m16n8k16.row.col.f32.bf16.bf16.f32 "
        "{%0,%1,%2,%3}, {%4,%5,%6,%7}, {%8,%9}, {%0,%1,%2,%3};"
        : "+f"(c[0]), "+f"(c[1]), "+f"(c[2]), "+f"(c[3])
        : "r"(a[0]), "r"(a[1]), "r"(a[2]), "r"(a[3]), "r"(b0), "r"(b1));
}

__device__ __forceinline__ int load_idx(const void* ei, long long pos, int is32) {
    if (is32) return ((const int*)ei)[pos];
    return (int)(((const long long*)ei)[pos]);
}

// ---------------- prep: detect dtype + zero deg + split W ----------------
__global__ void k_prep(const void* ei,
                       const float* __restrict__ Wl2, const float* __restrict__ Wr2,
                       const float* __restrict__ Wl3, const float* __restrict__ Wr3) {
    int idx = blockIdx.x * 1024 + threadIdx.x;   // 64 blocks x 1024 = 65536
    {
        int w = idx >> 14;
        int e = idx & 16383;
        const float* src = (w == 0) ? Wl2 : (w == 1) ? Wr2 : (w == 2) ? Wl3 : Wr3;
        float v = src[e];
        bf16 h, l;
        bsplit(v, h, l);
        g_Wh[w][e] = h;
        g_Wl[w][e] = l;
    }
    if (idx < N_NODES) g_deg[idx] = 0;
    if (blockIdx.x == 0) {
        __shared__ unsigned s_m[2];
        int t = threadIdx.x;
        if (t < 64) {
            long long v = ((const long long*)ei)[t];
            int bad = (v < 0 || v >= N_NODES) ? 1 : 0;
            unsigned m0 = __ballot_sync(0xffffffffu, bad);
            s_m[t >> 5] = m0;
        }
        __syncthreads();
        if (t == 0) g_is32 = (s_m[0] | s_m[1]) ? 1 : 0;
    }
}

// ---------------- CSR build (4 edges/thread for MLP) ----------------
__global__ void k_count(const void* ei) {
    int base = blockIdx.x * 1024 + threadIdx.x;
    int is32 = g_is32;
    int d[4];
    #pragma unroll
    for (int k = 0; k < 4; k++) {
        int e = base + k * 256;
        d[k] = (e < N_EDGES) ? load_idx(ei, (long long)N_EDGES + e, is32) : -1;
    }
    #pragma unroll
    for (int k = 0; k < 4; k++)
        if (d[k] >= 0) atomicAdd(&g_deg[d[k]], 1);
}

// pass 1: per-block exclusive scan + block sums
__global__ void k_scan1() {
    __shared__ int warp_sums[32];
    int tid = threadIdx.x;  // 1024
    int i = blockIdx.x * 1024 + tid;
    int v = (i < N_NODES) ? g_deg[i] : 0;
    int x = v;
    #pragma unroll
    for (int d = 1; d < 32; d <<= 1) {
        int y = __shfl_up_sync(0xffffffffu, x, d);
        if ((tid & 31) >= d) x += y;
    }
    if ((tid & 31) == 31) warp_sums[tid >> 5] = x;
    __syncthreads();
    if (tid < 32) {
        int w = warp_sums[tid];
        #pragma unroll
        for (int d = 1; d < 32; d <<= 1) {
            int y = __shfl_up_sync(0xffffffffu, w, d);
            if (tid >= d) w += y;
        }
        warp_sums[tid] = w;
    }
    __syncthreads();
    int incl = x + ((tid >= 32) ? warp_sums[(tid >> 5) - 1] : 0);
    if (i < N_NODES) g_off[i] = incl - v;
    if (tid == 0) g_bsum[blockIdx.x] = warp_sums[31];
}

// pass 2+3 merged: every block re-scans the block sums locally, then adds.
__global__ void k_scan23(int nblk) {
    __shared__ int s_pref[64];
    int tid = threadIdx.x;  // 1024
    if (tid < 32) {
        int v0 = (tid < nblk) ? g_bsum[tid] : 0;
        int v1 = (32 + tid < nblk) ? g_bsum[32 + tid] : 0;
        int x0 = v0, x1 = v1;
        #pragma unroll
        for (int d = 1; d < 32; d <<= 1) {
            int y0 = __shfl_up_sync(0xffffffffu, x0, d);
            int y1 = __shfl_up_sync(0xffffffffu, x1, d);
            if (tid >= d) { x0 += y0; x1 += y1; }
        }
        int tot0 = __shfl_sync(0xffffffffu, x0, 31);
        s_pref[tid] = x0 - v0;
        s_pref[32 + tid] = x1 - v1 + tot0;
    }
    __syncthreads();
    int i = blockIdx.x * 1024 + tid;
    if (i < N_NODES) {
        int off = g_off[i] + s_pref[blockIdx.x];
        g_off[i] = off;
        g_pos[i] = off;
    }
    if (blockIdx.x == 0 && tid == 0) g_off[N_NODES] = N_EDGES;
}

__global__ void k_fill(const void* ei) {
    int base = blockIdx.x * 1024 + threadIdx.x;
    int is32 = g_is32;
    int s[4], d[4];
    #pragma unroll
    for (int k = 0; k < 4; k++) {
        int e = base + k * 256;
        if (e < N_EDGES) {
            s[k] = load_idx(ei, e, is32);
            d[k] = load_idx(ei, (long long)N_EDGES + e, is32);
        } else d[k] = -1;
    }
    #pragma unroll
    for (int k = 0; k < 4; k++) {
        if (d[k] >= 0) {
            int p = atomicAdd(&g_pos[d[k]], 1);
            g_csr[p] = s[k];
        }
    }
}

// ---------------- layer-1 aggregation (F=16, f32) ----------------
__global__ void k_agg16(const float* __restrict__ x) {
    int warp = (blockIdx.x * blockDim.x + threadIdx.x) >> 5;
    int lane = threadIdx.x & 31;
    if (warp >= N_NODES) return;
    int beg = g_off[warp], end = g_off[warp + 1];
    float acc = 0.f;
    for (int i = beg; i < end; i++) {
        int s = g_csr[i];
        if (lane < 16) acc += x[(size_t)s * IN_DIM + lane];
    }
    float inv = 1.0f / fmaxf((float)(end - beg), 1.0f);
    if (lane < 16) g_agg[(size_t)warp * IN_DIM + lane] = acc * inv;
}

// F=128 mean agg: reads bf16 hi/lo activations, writes bf16 hi/lo agg.
__global__ void k_agg128(const bf16* __restrict__ Hh, const bf16* __restrict__ Hl,
                         bf16* __restrict__ oh, bf16* __restrict__ ol) {
    int warp = (blockIdx.x * blockDim.x + threadIdx.x) >> 5;
    int lane = threadIdx.x & 31;
    if (warp >= N_NODES) return;
    int beg = g_off[warp], end = g_off[warp + 1];
    float a0 = 0.f, a1 = 0.f, a2 = 0.f, a3 = 0.f;
    for (int i = beg; i < end; i++) {
        int s = g_csr[i];
        uint2 uh = *(const uint2*)(Hh + ((size_t)s << 7) + (lane << 2));
        uint2 ul = *(const uint2*)(Hl + ((size_t)s << 7) + (lane << 2));
        float2 f;
        f = __bfloat1622float2(*(__nv_bfloat162*)&uh.x); a0 += f.x; a1 += f.y;
        f = __bfloat1622float2(*(__nv_bfloat162*)&uh.y); a2 += f.x; a3 += f.y;
        f = __bfloat1622float2(*(__nv_bfloat162*)&ul.x); a0 += f.x; a1 += f.y;
        f = __bfloat1622float2(*(__nv_bfloat162*)&ul.y); a2 += f.x; a3 += f.y;
    }
    float inv = 1.0f / fmaxf((float)(end - beg), 1.0f);
    bf16 vh[4], vl[4];
    bsplit(a0 * inv, vh[0], vl[0]);
    bsplit(a1 * inv, vh[1], vl[1]);
    bsplit(a2 * inv, vh[2], vl[2]);
    bsplit(a3 * inv, vh[3], vl[3]);
    size_t o = ((size_t)warp << 7) + (lane << 2);
    *(uint2*)(oh + o) = *(const uint2*)vh;
    *(uint2*)(ol + o) = *(const uint2*)vl;
}

// ---------------- layer-1 FFMA GEMM (K=16 per segment), hi/lo out ----------
__global__ __launch_bounds__(256)
void k_sage_gemm(const float* __restrict__ A1, const float* __restrict__ A2,
                 const float* __restrict__ W1, const float* __restrict__ W2,
                 const float* __restrict__ bias,
                 bf16* __restrict__ out_hi, bf16* __restrict__ out_lo,
                 int K)
{
    __shared__ float As[16][128];
    __shared__ float Ws[16][128];
    int tid = threadIdx.x;
    int tx = tid & 15;
    int ty = tid >> 4;
    int row0 = blockIdx.x * 128;

    float c[8][8];
    #pragma unroll
    for (int i = 0; i < 8; i++)
        #pragma unroll
        for (int j = 0; j < 8; j++) c[i][j] = 0.f;

    #pragma unroll
    for (int seg = 0; seg < 2; seg++) {
        const float* A = seg ? A2 : A1;
        const float* W = seg ? W2 : W1;
        for (int kk = 0; kk < K; kk += 16) {
            #pragma unroll
            for (int t = 0; t < 2; t++) {
                int idx = tid + t * 256;
                int m  = idx >> 2;
                int kq = idx & 3;
                int gm = row0 + m;
                float4 v = make_float4(0.f, 0.f, 0.f, 0.f);
                if (gm < N_NODES)
                    v = *(const float4*)(A + (size_t)gm * K + kk + kq * 4);
                As[kq * 4 + 0][m] = v.x; As[kq * 4 + 1][m] = v.y;
                As[kq * 4 + 2][m] = v.z; As[kq * 4 + 3][m] = v.w;
                float4 w = *(const float4*)(W + (size_t)m * K + kk + kq * 4);
                Ws[kq * 4 + 0][m] = w.x; Ws[kq * 4 + 1][m] = w.y;
                Ws[kq * 4 + 2][m] = w.z; Ws[kq * 4 + 3][m] = w.w;
            }
            __syncthreads();
            #pragma unroll
            for (int k = 0; k < 16; k++) {
                float a[8], w[8];
                *(float4*)&a[0] = *(const float4*)&As[k][ty * 8];
                *(float4*)&a[4] = *(const float4*)&As[k][ty * 8 + 4];
                *(float4*)&w[0] = *(const float4*)&Ws[k][tx * 8];
                *(float4*)&w[4] = *(const float4*)&Ws[k][tx * 8 + 4];
                #pragma unroll
                for (int i = 0; i < 8; i++)
                    #pragma unroll
                    for (int j = 0; j < 8; j++)
                        c[i][j] += a[i] * w[j];
            }
            __syncthreads();
        }
    }

    #pragma unroll
    for (int i = 0; i < 8; i++) {
        int gm = row0 + ty * 8 + i;
        if (gm >= N_NODES) continue;
        #pragma unroll
        for (int j = 0; j < 8; j += 4) {
            int gn = tx * 8 + j;
            bf16 vh[4], vl[4];
            #pragma unroll
            for (int q = 0; q < 4; q++) {
                float v = fmaxf(c[i][j + q] + bias[gn + q], 0.f);
                bsplit(v, vh[q], vl[q]);
            }
            *(uint2*)(out_hi + (size_t)gm * 128 + gn) = *(const uint2*)vh;
            *(uint2*)(out_lo + (size_t)gm * 128 + gn) = *(const uint2*)vl;
        }
    }
}

// ---------------- bf16 split-HMMA GEMM (layers 2+3) ----------------
// out[M,128] = relu([A1|A2](M,256) @ [B1|B2](128,256)^T + bias)
#define SK 40   // smem row stride in halves (conflict-free fragment loads)

__global__ __launch_bounds__(256, 2)
void k_mma_gemm(const bf16* __restrict__ A1h, const bf16* __restrict__ A1l,
                const bf16* __restrict__ A2h, const bf16* __restrict__ A2l,
                const bf16* __restrict__ B1h, const bf16* __restrict__ B1l,
                const bf16* __restrict__ B2h, const bf16* __restrict__ B2l,
                const float* __restrict__ bias,
                float* __restrict__ outf,
                bf16* __restrict__ outh, bf16* __restrict__ outl,
                int flags)   // 1 = write f32, 2 = write hi/lo
{
    __shared__ bf16 sAh[128][SK], sAl[128][SK], sWh[128][SK], sWl[128][SK];
    int tid = threadIdx.x;
    int wid = tid >> 5;
    int lane = tid & 31;
    int tg = lane & 3;
    int gp = lane >> 2;
    int warp_m = wid & 3;
    int warp_n = wid >> 2;
    int row0 = blockIdx.x * 128;

    float c[2][8][4];
    #pragma unroll
    for (int mt = 0; mt < 2; mt++)
        #pragma unroll
        for (int nt = 0; nt < 8; nt++)
            #pragma unroll
            for (int q = 0; q < 4; q++) c[mt][nt][q] = 0.f;

    for (int ch = 0; ch < 8; ch++) {
        int seg = ch >> 2;
        int k0 = (ch & 3) * 32;
        const bf16* Ah = seg ? A2h : A1h;
        const bf16* Al = seg ? A2l : A1l;
        const bf16* Bh = seg ? B2h : B1h;
        const bf16* Bl = seg ? B2l : B1l;

        if (ch) __syncthreads();
        #pragma unroll
        for (int t = 0; t < 2; t++) {
            int idx = tid + t * 256;   // 0..511
            int m = idx >> 2;          // 0..127
            int q = idx & 3;           // 8-half group within 32
            int gm = row0 + m;
            float4 va = make_float4(0.f, 0.f, 0.f, 0.f), vb = va;
            if (gm < N_NODES) {
                va = *(const float4*)(Ah + (size_t)gm * 128 + k0 + q * 8);
                vb = *(const float4*)(Al + (size_t)gm * 128 + k0 + q * 8);
            }
            *(float4*)&sAh[m][q * 8] = va;
            *(float4*)&sAl[m][q * 8] = vb;
            float4 wh = *(const float4*)(Bh + (size_t)m * 128 + k0 + q * 8);
            float4 wl = *(const float4*)(Bl + (size_t)m * 128 + k0 + q * 8);
            *(float4*)&sWh[m][q * 8] = wh;
            *(float4*)&sWl[m][q * 8] = wl;
        }
        __syncthreads();

        #pragma unroll
        for (int ks = 0; ks < 2; ks++) {
            int kh = ks * 16;
            uint32_t ah[2][4], al[2][4];
            #pragma unroll
            for (int mt = 0; mt < 2; mt++) {
                int r = warp_m * 32 + mt * 16 + gp;
                ah[mt][0] = *(const uint32_t*)&sAh[r    ][kh + 2 * tg];
                ah[mt][1] = *(const uint32_t*)&sAh[r + 8][kh + 2 * tg];
                ah[mt][2] = *(const uint32_t*)&sAh[r    ][kh + 8 + 2 * tg];
                ah[mt][3] = *(const uint32_t*)&sAh[r + 8][kh + 8 + 2 * tg];
                al[mt][0] = *(const uint32_t*)&sAl[r    ][kh + 2 * tg];
                al[mt][1] = *(const uint32_t*)&sAl[r + 8][kh + 2 * tg];
                al[mt][2] = *(const uint32_t*)&sAl[r    ][kh + 8 + 2 * tg];
                al[mt][3] = *(const uint32_t*)&sAl[r + 8][kh + 8 + 2 * tg];
            }
            #pragma unroll
            for (int nt = 0; nt < 8; nt++) {
                int n = warp_n * 64 + nt * 8 + gp;
                uint32_t bh0 = *(const uint32_t*)&sWh[n][kh + 2 * tg];
                uint32_t bh1 = *(const uint32_t*)&sWh[n][kh + 8 + 2 * tg];
                uint32_t bl0 = *(const uint32_t*)&sWl[n][kh + 2 * tg];
                uint32_t bl1 = *(const uint32_t*)&sWl[n][kh + 8 + 2 * tg];
                #pragma unroll
                for (int mt = 0; mt < 2; mt++) {
                    mma_bf16(c[mt][nt], ah[mt], bh0, bh1);
                    mma_bf16(c[mt][nt], ah[mt], bl0, bl1);
                    mma_bf16(c[mt][nt], al[mt], bh0, bh1);
                }
            }
        }
    }

    // epilogue
    #pragma unroll
    for (int mt = 0; mt < 2; mt++) {
        int row = row0 + warp_m * 32 + mt * 16 + gp;
        #pragma unroll
        for (int nt = 0; nt < 8; nt++) {
            int col = warp_n * 64 + nt * 8 + 2 * tg;
            float b0 = bias[col], b1 = bias[col + 1];
            #pragma unroll
            for (int half = 0; half < 2; half++) {
                int r = row + half * 8;
                if (r < N_NODES) {
                    float v0 = fmaxf(c[mt][nt][half * 2 + 0] + b0, 0.f);
                    float v1 = fmaxf(c[mt][nt][half * 2 + 1] + b1, 0.f);
                    if (flags & 1)
                        *(float2*)(outf + (size_t)r * 128 + col) = make_float2(v0, v1);
                    if (flags & 2) {
                        bf16 h0, l0, h1, l1;
                        bsplit(v0, h0, l0); bsplit(v1, h1, l1);
                        bf16 hh[2] = {h0, h1}, ll[2] = {l0, l1};
                        *(uint32_t*)(outh + (size_t)r * 128 + col) = *(const uint32_t*)hh;
                        *(uint32_t*)(outl + (size_t)r * 128 + col) = *(const uint32_t*)ll;
                    }
                }
            }
        }
    }
}

// ---------------- head ----------------
__global__ void k_head(const float* __restrict__ h, const float* __restrict__ Wh,
                       const float* __restrict__ bh, float* __restrict__ out)
{
    int warp = (blockIdx.x * blockDim.x + threadIdx.x) >> 5;
    int lane = threadIdx.x & 31;
    if (warp >= N_NODES) return;
    float4 hv = *(const float4*)(h + ((size_t)warp << 7) + (lane << 2));
    float p[4];
    #pragma unroll
    for (int o = 0; o < 4; o++) {
        float4 w = *(const float4*)(Wh + o * 128 + (lane << 2));
        float s = hv.x * w.x + hv.y * w.y + hv.z * w.z + hv.w * w.w;
        #pragma unroll
        for (int d = 16; d > 0; d >>= 1) s += __shfl_xor_sync(0xffffffffu, s, d);
        p[o] = s;
    }
    if (lane == 0) {
        float4 v = make_float4(p[0] + bh[0], p[1] + bh[1], p[2] + bh[2], p[3] + bh[3]);
        *(float4*)(out + (size_t)warp * 4) = v;
    }
}

// ---------------- launch ----------------
extern "C" void kernel_launch(void* const* d_in, const int* in_sizes, int n_in,
                              void* d_out, int out_size)
{
    const float* x   = (const float*)d_in[0];
    const void*  ei  = d_in[1];
    const float* Wl1 = (const float*)d_in[2];
    const float* Wr1 = (const float*)d_in[3];
    const float* b1  = (const float*)d_in[4];
    const float* Wl2 = (const float*)d_in[5];
    const float* Wr2 = (const float*)d_in[6];
    const float* b2  = (const float*)d_in[7];
    const float* Wl3 = (const float*)d_in[8];
    const float* Wr3 = (const float*)d_in[9];
    const float* b3  = (const float*)d_in[10];
    const float* Wh  = (const float*)d_in[11];
    const float* bh  = (const float*)d_in[12];
    float* out = (float*)d_out;

    float *p_agg, *p_hf;
    bf16 *p_aggh, *p_aggl, *p_h1h, *p_h1l, *p_h2h, *p_h2l, *p_Whs, *p_Wls;
    cudaGetSymbolAddress((void**)&p_agg,  g_agg);
    cudaGetSymbolAddress((void**)&p_hf,   g_hf);
    cudaGetSymbolAddress((void**)&p_aggh, g_aggh);
    cudaGetSymbolAddress((void**)&p_aggl, g_aggl);
    cudaGetSymbolAddress((void**)&p_h1h,  g_h1h);
    cudaGetSymbolAddress((void**)&p_h1l,  g_h1l);
    cudaGetSymbolAddress((void**)&p_h2h,  g_h2h);
    cudaGetSymbolAddress((void**)&p_h2l,  g_h2l);
    cudaGetSymbolAddress((void**)&p_Whs,  g_Wh);
    cudaGetSymbolAddress((void**)&p_Wls,  g_Wl);

    const int WB = (N_NODES + 7) / 8;            // warp-per-node, 256 thr
    const int GB = (N_NODES + 127) / 128;        // 391
    const int SB = (N_NODES + 1023) / 1024;      // 49
    const int CB = (N_EDGES + 1023) / 1024;      // 586

    // graph structure + W split
    k_prep<<<64, 1024>>>(ei, Wl2, Wr2, Wl3, Wr3);
    k_count<<<CB, 256>>>(ei);
    k_scan1<<<SB, 1024>>>();
    k_scan23<<<SB, 1024>>>(SB);
    k_fill<<<CB, 256>>>(ei);

    const int HH = HIDDEN * HIDDEN;

    // layer 1 (FFMA, K=16) -> h1 hi/lo
    k_agg16<<<WB, 256>>>(x);
    k_sage_gemm<<<GB, 256>>>(p_agg, x, Wl1, Wr1, b1, p_h1h, p_h1l, IN_DIM);

    // layer 2 (bf16 split HMMA) -> h2 hi/lo
    k_agg128<<<WB, 256>>>(p_h1h, p_h1l, p_aggh, p_aggl);
    k_mma_gemm<<<GB, 256>>>(p_aggh, p_aggl, p_h1h, p_h1l,
                            p_Whs + 0 * HH, p_Wls + 0 * HH,
                            p_Whs + 1 * HH, p_Wls + 1 * HH,
                            b2, nullptr, p_h2h, p_h2l, 2);

    // layer 3 (bf16 split HMMA) -> f32 for head
    k_agg128<<<WB, 256>>>(p_h2h, p_h2l, p_aggh, p_aggl);
    k_mma_gemm<<<GB, 256>>>(p_aggh, p_aggl, p_h2h, p_h2l,
                            p_Whs + 2 * HH, p_Wls + 2 * HH,
                            p_Whs + 3 * HH, p_Wls + 3 * HH,
                            b3, p_hf, nullptr, nullptr, 1);

    // head
    k_head<<<WB, 256>>>(p_hf, Wh, bh, out);
}

// round 8
// speedup vs baseline: 2.2010x; 1.0411x over previous
#include <cuda_runtime.h>
#include <cuda_bf16.h>
#include <cstdint>
#include <cstddef>

#define N_NODES 50000
#define N_EDGES 600000
#define IN_DIM  16
#define HIDDEN  128
#define OUT_DIM 4

typedef __nv_bfloat16 bf16;

// ---------------- device scratch (static: no allocs allowed) ----------------
__device__ int   g_deg[N_NODES];
__device__ int   g_off[N_NODES + 1];
__device__ int   g_pos[N_NODES];
__device__ int   g_csr[N_EDGES];
__device__ int   g_is32;
__device__ int   g_bsum[80];

__device__ float g_agg[(size_t)N_NODES * IN_DIM];      // layer1 agg (f32)
__device__ float g_hf [(size_t)N_NODES * HIDDEN];      // layer3 f32 out (head input)
// bf16 hi/lo splits
__device__ bf16  g_aggh[(size_t)N_NODES * HIDDEN];
__device__ bf16  g_aggl[(size_t)N_NODES * HIDDEN];
__device__ bf16  g_h1h[(size_t)N_NODES * HIDDEN];
__device__ bf16  g_h1l[(size_t)N_NODES * HIDDEN];
__device__ bf16  g_h2h[(size_t)N_NODES * HIDDEN];
__device__ bf16  g_h2l[(size_t)N_NODES * HIDDEN];
// W splits: order Wl2, Wr2, Wl3, Wr3
__device__ bf16  g_Wh[4][HIDDEN * HIDDEN];
__device__ bf16  g_Wl[4][HIDDEN * HIDDEN];

// ---------------- helpers ----------------
__device__ __forceinline__ void bsplit(float x, bf16& h, bf16& l) {
    h = __float2bfloat16_rn(x);
    l = __float2bfloat16_rn(x - __bfloat162float(h));
}

__device__ __forceinline__ void mma_bf16(float c[4], const uint32_t a[4],
                                         uint32_t b0, uint32_t b1) {
    asm volatile(
        "mma.sync.aligned.m16n8k16.row.col.f32.bf16.bf16.f32 "
        "{%0,%1,%2,%3}, {%4,%5,%6,%7}, {%8,%9}, {%0,%1,%2,%3};"
        : "+f"(c[0]), "+f"(c[1]), "+f"(c[2]), "+f"(c[3])
        : "r"(a[0]), "r"(a[1]), "r"(a[2]), "r"(a[3]), "r"(b0), "r"(b1));
}

#define LDSM4(r, addr) \
    asm volatile("ldmatrix.sync.aligned.m8n8.x4.shared.b16 {%0,%1,%2,%3}, [%4];" \
        : "=r"((r)[0]), "=r"((r)[1]), "=r"((r)[2]), "=r"((r)[3]) : "r"(addr))
#define LDSM2(r0, r1, addr) \
    asm volatile("ldmatrix.sync.aligned.m8n8.x2.shared.b16 {%0,%1}, [%2];" \
        : "=r"(r0), "=r"(r1) : "r"(addr))
#define CP16(dst, src, sz) \
    asm volatile("cp.async.ca.shared.global [%0], [%1], 16, %2;" \
        :: "r"(dst), "l"(src), "r"(sz))
#define CP_COMMIT() asm volatile("cp.async.commit_group;")
#define CP_WAIT1()  asm volatile("cp.async.wait_group 1;")
#define CP_WAIT0()  asm volatile("cp.async.wait_group 0;")

__device__ __forceinline__ int load_idx(const void* ei, long long pos, int is32) {
    if (is32) return ((const int*)ei)[pos];
    return (int)(((const long long*)ei)[pos]);
}

// ---------------- prep: detect dtype + zero deg + split W ----------------
__global__ void k_prep(const void* ei,
                       const float* __restrict__ Wl2, const float* __restrict__ Wr2,
                       const float* __restrict__ Wl3, const float* __restrict__ Wr3) {
    int idx = blockIdx.x * 1024 + threadIdx.x;   // 64 blocks x 1024 = 65536
    {
        int w = idx >> 14;
        int e = idx & 16383;
        const float* src = (w == 0) ? Wl2 : (w == 1) ? Wr2 : (w == 2) ? Wl3 : Wr3;
        float v = src[e];
        bf16 h, l;
        bsplit(v, h, l);
        g_Wh[w][e] = h;
        g_Wl[w][e] = l;
    }
    if (idx < N_NODES) g_deg[idx] = 0;
    if (blockIdx.x == 0) {
        __shared__ unsigned s_m[2];
        int t = threadIdx.x;
        if (t < 64) {
            long long v = ((const long long*)ei)[t];
            int bad = (v < 0 || v >= N_NODES) ? 1 : 0;
            unsigned m0 = __ballot_sync(0xffffffffu, bad);
            s_m[t >> 5] = m0;
        }
        __syncthreads();
        if (t == 0) g_is32 = (s_m[0] | s_m[1]) ? 1 : 0;
    }
}

// ---------------- CSR build (4 edges/thread for MLP) ----------------
__global__ void k_count(const void* ei) {
    int base = blockIdx.x * 1024 + threadIdx.x;
    int is32 = g_is32;
    int d[4];
    #pragma unroll
    for (int k = 0; k < 4; k++) {
        int e = base + k * 256;
        d[k] = (e < N_EDGES) ? load_idx(ei, (long long)N_EDGES + e, is32) : -1;
    }
    #pragma unroll
    for (int k = 0; k < 4; k++)
        if (d[k] >= 0) atomicAdd(&g_deg[d[k]], 1);
}

// pass 1: per-block exclusive scan + block sums
__global__ void k_scan1() {
    __shared__ int warp_sums[32];
    int tid = threadIdx.x;  // 1024
    int i = blockIdx.x * 1024 + tid;
    int v = (i < N_NODES) ? g_deg[i] : 0;
    int x = v;
    #pragma unroll
    for (int d = 1; d < 32; d <<= 1) {
        int y = __shfl_up_sync(0xffffffffu, x, d);
        if ((tid & 31) >= d) x += y;
    }
    if ((tid & 31) == 31) warp_sums[tid >> 5] = x;
    __syncthreads();
    if (tid < 32) {
        int w = warp_sums[tid];
        #pragma unroll
        for (int d = 1; d < 32; d <<= 1) {
            int y = __shfl_up_sync(0xffffffffu, w, d);
            if (tid >= d) w += y;
        }
        warp_sums[tid] = w;
    }
    __syncthreads();
    int incl = x + ((tid >= 32) ? warp_sums[(tid >> 5) - 1] : 0);
    if (i < N_NODES) g_off[i] = incl - v;
    if (tid == 0) g_bsum[blockIdx.x] = warp_sums[31];
}

// pass 2+3 merged
__global__ void k_scan23(int nblk) {
    __shared__ int s_pref[64];
    int tid = threadIdx.x;  // 1024
    if (tid < 32) {
        int v0 = (tid < nblk) ? g_bsum[tid] : 0;
        int v1 = (32 + tid < nblk) ? g_bsum[32 + tid] : 0;
        int x0 = v0, x1 = v1;
        #pragma unroll
        for (int d = 1; d < 32; d <<= 1) {
            int y0 = __shfl_up_sync(0xffffffffu, x0, d);
            int y1 = __shfl_up_sync(0xffffffffu, x1, d);
            if (tid >= d) { x0 += y0; x1 += y1; }
        }
        int tot0 = __shfl_sync(0xffffffffu, x0, 31);
        s_pref[tid] = x0 - v0;
        s_pref[32 + tid] = x1 - v1 + tot0;
    }
    __syncthreads();
    int i = blockIdx.x * 1024 + tid;
    if (i < N_NODES) {
        int off = g_off[i] + s_pref[blockIdx.x];
        g_off[i] = off;
        g_pos[i] = off;
    }
    if (blockIdx.x == 0 && tid == 0) g_off[N_NODES] = N_EDGES;
}

__global__ void k_fill(const void* ei) {
    int base = blockIdx.x * 1024 + threadIdx.x;
    int is32 = g_is32;
    int s[4], d[4];
    #pragma unroll
    for (int k = 0; k < 4; k++) {
        int e = base + k * 256;
        if (e < N_EDGES) {
            s[k] = load_idx(ei, e, is32);
            d[k] = load_idx(ei, (long long)N_EDGES + e, is32);
        } else d[k] = -1;
    }
    #pragma unroll
    for (int k = 0; k < 4; k++) {
        if (d[k] >= 0) {
            int p = atomicAdd(&g_pos[d[k]], 1);
            g_csr[p] = s[k];
        }
    }
}

// ---------------- layer-1 aggregation (F=16, f32) ----------------
__global__ void k_agg16(const float* __restrict__ x) {
    int warp = (blockIdx.x * blockDim.x + threadIdx.x) >> 5;
    int lane = threadIdx.x & 31;
    if (warp >= N_NODES) return;
    int beg = g_off[warp], end = g_off[warp + 1];
    float acc = 0.f;
    for (int i = beg; i < end; i++) {
        int s = g_csr[i];
        if (lane < 16) acc += x[(size_t)s * IN_DIM + lane];
    }
    float inv = 1.0f / fmaxf((float)(end - beg), 1.0f);
    if (lane < 16) g_agg[(size_t)warp * IN_DIM + lane] = acc * inv;
}

// F=128 mean agg, unroll x4 for MLP: 4 indices then 8 independent gathers.
__global__ void k_agg128(const bf16* __restrict__ Hh, const bf16* __restrict__ Hl,
                         bf16* __restrict__ oh, bf16* __restrict__ ol) {
    int warp = (blockIdx.x * blockDim.x + threadIdx.x) >> 5;
    int lane = threadIdx.x & 31;
    if (warp >= N_NODES) return;
    int beg = g_off[warp], end = g_off[warp + 1];
    float a0 = 0.f, a1 = 0.f, a2 = 0.f, a3 = 0.f;
    int loff = lane << 2;
    int i = beg;
    for (; i + 4 <= end; i += 4) {
        int s0 = g_csr[i], s1 = g_csr[i + 1], s2 = g_csr[i + 2], s3 = g_csr[i + 3];
        uint2 h0 = *(const uint2*)(Hh + ((size_t)s0 << 7) + loff);
        uint2 l0 = *(const uint2*)(Hl + ((size_t)s0 << 7) + loff);
        uint2 h1 = *(const uint2*)(Hh + ((size_t)s1 << 7) + loff);
        uint2 l1 = *(const uint2*)(Hl + ((size_t)s1 << 7) + loff);
        uint2 h2 = *(const uint2*)(Hh + ((size_t)s2 << 7) + loff);
        uint2 l2 = *(const uint2*)(Hl + ((size_t)s2 << 7) + loff);
        uint2 h3 = *(const uint2*)(Hh + ((size_t)s3 << 7) + loff);
        uint2 l3 = *(const uint2*)(Hl + ((size_t)s3 << 7) + loff);
        float2 f;
        f = __bfloat1622float2(*(__nv_bfloat162*)&h0.x); a0 += f.x; a1 += f.y;
        f = __bfloat1622float2(*(__nv_bfloat162*)&h0.y); a2 += f.x; a3 += f.y;
        f = __bfloat1622float2(*(__nv_bfloat162*)&l0.x); a0 += f.x; a1 += f.y;
        f = __bfloat1622float2(*(__nv_bfloat162*)&l0.y); a2 += f.x; a3 += f.y;
        f = __bfloat1622float2(*(__nv_bfloat162*)&h1.x); a0 += f.x; a1 += f.y;
        f = __bfloat1622float2(*(__nv_bfloat162*)&h1.y); a2 += f.x; a3 += f.y;
        f = __bfloat1622float2(*(__nv_bfloat162*)&l1.x); a0 += f.x; a1 += f.y;
        f = __bfloat1622float2(*(__nv_bfloat162*)&l1.y); a2 += f.x; a3 += f.y;
        f = __bfloat1622float2(*(__nv_bfloat162*)&h2.x); a0 += f.x; a1 += f.y;
        f = __bfloat1622float2(*(__nv_bfloat162*)&h2.y); a2 += f.x; a3 += f.y;
        f = __bfloat1622float2(*(__nv_bfloat162*)&l2.x); a0 += f.x; a1 += f.y;
        f = __bfloat1622float2(*(__nv_bfloat162*)&l2.y); a2 += f.x; a3 += f.y;
        f = __bfloat1622float2(*(__nv_bfloat162*)&h3.x); a0 += f.x; a1 += f.y;
        f = __bfloat1622float2(*(__nv_bfloat162*)&h3.y); a2 += f.x; a3 += f.y;
        f = __bfloat1622float2(*(__nv_bfloat162*)&l3.x); a0 += f.x; a1 += f.y;
        f = __bfloat1622float2(*(__nv_bfloat162*)&l3.y); a2 += f.x; a3 += f.y;
    }
    for (; i < end; i++) {
        int s = g_csr[i];
        uint2 uh = *(const uint2*)(Hh + ((size_t)s << 7) + loff);
        uint2 ul = *(const uint2*)(Hl + ((size_t)s << 7) + loff);
        float2 f;
        f = __bfloat1622float2(*(__nv_bfloat162*)&uh.x); a0 += f.x; a1 += f.y;
        f = __bfloat1622float2(*(__nv_bfloat162*)&uh.y); a2 += f.x; a3 += f.y;
        f = __bfloat1622float2(*(__nv_bfloat162*)&ul.x); a0 += f.x; a1 += f.y;
        f = __bfloat1622float2(*(__nv_bfloat162*)&ul.y); a2 += f.x; a3 += f.y;
    }
    float inv = 1.0f / fmaxf((float)(end - beg), 1.0f);
    bf16 vh[4], vl[4];
    bsplit(a0 * inv, vh[0], vl[0]);
    bsplit(a1 * inv, vh[1], vl[1]);
    bsplit(a2 * inv, vh[2], vl[2]);
    bsplit(a3 * inv, vh[3], vl[3]);
    size_t o = ((size_t)warp << 7) + loff;
    *(uint2*)(oh + o) = *(const uint2*)vh;
    *(uint2*)(ol + o) = *(const uint2*)vl;
}

// ---------------- layer-1 FFMA GEMM (K=16 per segment), hi/lo out ----------
__global__ __launch_bounds__(256)
void k_sage_gemm(const float* __restrict__ A1, const float* __restrict__ A2,
                 const float* __restrict__ W1, const float* __restrict__ W2,
                 const float* __restrict__ bias,
                 bf16* __restrict__ out_hi, bf16* __restrict__ out_lo,
                 int K)
{
    __shared__ float As[16][128];
    __shared__ float Ws[16][128];
    int tid = threadIdx.x;
    int tx = tid & 15;
    int ty = tid >> 4;
    int row0 = blockIdx.x * 128;

    float c[8][8];
    #pragma unroll
    for (int i = 0; i < 8; i++)
        #pragma unroll
        for (int j = 0; j < 8; j++) c[i][j] = 0.f;

    #pragma unroll
    for (int seg = 0; seg < 2; seg++) {
        const float* A = seg ? A2 : A1;
        const float* W = seg ? W2 : W1;
        for (int kk = 0; kk < K; kk += 16) {
            #pragma unroll
            for (int t = 0; t < 2; t++) {
                int idx = tid + t * 256;
                int m  = idx >> 2;
                int kq = idx & 3;
                int gm = row0 + m;
                float4 v = make_float4(0.f, 0.f, 0.f, 0.f);
                if (gm < N_NODES)
                    v = *(const float4*)(A + (size_t)gm * K + kk + kq * 4);
                As[kq * 4 + 0][m] = v.x; As[kq * 4 + 1][m] = v.y;
                As[kq * 4 + 2][m] = v.z; As[kq * 4 + 3][m] = v.w;
                float4 w = *(const float4*)(W + (size_t)m * K + kk + kq * 4);
                Ws[kq * 4 + 0][m] = w.x; Ws[kq * 4 + 1][m] = w.y;
                Ws[kq * 4 + 2][m] = w.z; Ws[kq * 4 + 3][m] = w.w;
            }
            __syncthreads();
            #pragma unroll
            for (int k = 0; k < 16; k++) {
                float a[8], w[8];
                *(float4*)&a[0] = *(const float4*)&As[k][ty * 8];
                *(float4*)&a[4] = *(const float4*)&As[k][ty * 8 + 4];
                *(float4*)&w[0] = *(const float4*)&Ws[k][tx * 8];
                *(float4*)&w[4] = *(const float4*)&Ws[k][tx * 8 + 4];
                #pragma unroll
                for (int i = 0; i < 8; i++)
                    #pragma unroll
                    for (int j = 0; j < 8; j++)
                        c[i][j] += a[i] * w[j];
            }
            __syncthreads();
        }
    }

    #pragma unroll
    for (int i = 0; i < 8; i++) {
        int gm = row0 + ty * 8 + i;
        if (gm >= N_NODES) continue;
        #pragma unroll
        for (int j = 0; j < 8; j += 4) {
            int gn = tx * 8 + j;
            bf16 vh[4], vl[4];
            #pragma unroll
            for (int q = 0; q < 4; q++) {
                float v = fmaxf(c[i][j + q] + bias[gn + q], 0.f);
                bsplit(v, vh[q], vl[q]);
            }
            *(uint2*)(out_hi + (size_t)gm * 128 + gn) = *(const uint2*)vh;
            *(uint2*)(out_lo + (size_t)gm * 128 + gn) = *(const uint2*)vl;
        }
    }
}

// ---------------- bf16 split-HMMA GEMM, cp.async pipelined + ldmatrix -------
// out[M,128] = relu([A1|A2](M,256) @ [B1|B2](128,256)^T + bias)
// Per chunk tile: 128 rows x 32 halves, row stride 40 halves (80 B).
// Stage layout (bytes): Ah +0, Al +10240, Wh +20480, Wl +30720; stage 40960.
#define TSTRIDE 80          // bytes per smem row
#define TILE_AL 10240
#define TILE_WH 20480
#define TILE_WL 30720
#define STAGE_B 40960

__global__ __launch_bounds__(256, 2)
void k_mma_gemm(const bf16* __restrict__ A1h, const bf16* __restrict__ A1l,
                const bf16* __restrict__ A2h, const bf16* __restrict__ A2l,
                const bf16* __restrict__ B1h, const bf16* __restrict__ B1l,
                const bf16* __restrict__ B2h, const bf16* __restrict__ B2l,
                const float* __restrict__ bias,
                float* __restrict__ outf,
                bf16* __restrict__ outh, bf16* __restrict__ outl,
                int flags)   // 1 = write f32, 2 = write hi/lo
{
    extern __shared__ char sm[];
    uint32_t smb = (uint32_t)__cvta_generic_to_shared(sm);

    int tid = threadIdx.x;
    int wid = tid >> 5;
    int lane = tid & 31;
    int warp_m = wid & 3;
    int warp_n = wid >> 2;
    int row0 = blockIdx.x * 128;

    // ldmatrix lane-derived byte offsets
    int g = lane >> 3;
    uint32_t aoff = (uint32_t)(((lane & 7) + ((g & 1) << 3)) * TSTRIDE + (g >> 1) * 16);
    uint32_t boff = (uint32_t)((lane & 7) * TSTRIDE + ((lane >> 3) & 1) * 16);

    // loader thread mapping
    int lm = (tid >> 2);            // row 0..63 for t=0; +64 for t=1
    int lq = (tid & 3);             // 16B group within 32 halves
    uint32_t dof0 = (uint32_t)(lm * TSTRIDE + lq * 16);
    uint32_t dof1 = (uint32_t)((lm + 64) * TSTRIDE + lq * 16);

    float c[2][8][4];
    #pragma unroll
    for (int mt = 0; mt < 2; mt++)
        #pragma unroll
        for (int nt = 0; nt < 8; nt++)
            #pragma unroll
            for (int q = 0; q < 4; q++) c[mt][nt][q] = 0.f;

    // --- chunk loader (8 cp.async x 16B per thread, 4 tiles) ---
    auto load_chunk = [&](int ch, int stage) {
        int seg = ch >> 2;
        int k0 = (ch & 3) * 32;
        const bf16* Ah = seg ? A2h : A1h;
        const bf16* Al = seg ? A2l : A1l;
        const bf16* Bh = seg ? B2h : B1h;
        const bf16* Bl = seg ? B2l : B1l;
        uint32_t SB = smb + stage * STAGE_B;
        #pragma unroll
        for (int t = 0; t < 2; t++) {
            int m = (t == 0) ? lm : lm + 64;
            uint32_t dof = (t == 0) ? dof0 : dof1;
            int gm = row0 + m;
            uint32_t sz = (gm < N_NODES) ? 16u : 0u;
            size_t gmc = (gm < N_NODES) ? (size_t)gm : 0;
            CP16(SB + dof,           Ah + (gmc << 7) + k0 + lq * 8, sz);
            CP16(SB + TILE_AL + dof, Al + (gmc << 7) + k0 + lq * 8, sz);
            CP16(SB + TILE_WH + dof, Bh + ((size_t)m << 7) + k0 + lq * 8, 16u);
            CP16(SB + TILE_WL + dof, Bl + ((size_t)m << 7) + k0 + lq * 8, 16u);
        }
    };

    load_chunk(0, 0);
    CP_COMMIT();

    for (int ch = 0; ch < 8; ch++) {
        if (ch < 7) {
            load_chunk(ch + 1, (ch + 1) & 1);
            CP_COMMIT();
            CP_WAIT1();
        } else {
            CP_WAIT0();
        }
        __syncthreads();

        uint32_t SB = smb + (ch & 1) * STAGE_B;
        #pragma unroll
        for (int ks = 0; ks < 2; ks++) {
            uint32_t kso = (uint32_t)(ks * 32);
            uint32_t ah[2][4], al[2][4];
            #pragma unroll
            for (int mt = 0; mt < 2; mt++) {
                uint32_t abase = SB + (uint32_t)((warp_m * 32 + mt * 16) * TSTRIDE) + kso + aoff;
                LDSM4(ah[mt], abase);
                LDSM4(al[mt], abase + TILE_AL);
            }
            #pragma unroll
            for (int nt = 0; nt < 8; nt++) {
                uint32_t bbase = SB + TILE_WH + (uint32_t)((warp_n * 64 + nt * 8) * TSTRIDE) + kso + boff;
                uint32_t bh0, bh1, bl0, bl1;
                LDSM2(bh0, bh1, bbase);
                LDSM2(bl0, bl1, bbase + (TILE_WL - TILE_WH));
                #pragma unroll
                for (int mt = 0; mt < 2; mt++) {
                    mma_bf16(c[mt][nt], ah[mt], bh0, bh1);
                    mma_bf16(c[mt][nt], ah[mt], bl0, bl1);
                    mma_bf16(c[mt][nt], al[mt], bh0, bh1);
                }
            }
        }
        __syncthreads();
    }

    // epilogue
    int tg = lane & 3;
    int gp = lane >> 2;
    #pragma unroll
    for (int mt = 0; mt < 2; mt++) {
        int row = row0 + warp_m * 32 + mt * 16 + gp;
        #pragma unroll
        for (int nt = 0; nt < 8; nt++) {
            int col = warp_n * 64 + nt * 8 + 2 * tg;
            float b0 = bias[col], b1 = bias[col + 1];
            #pragma unroll
            for (int half = 0; half < 2; half++) {
                int r = row + half * 8;
                if (r < N_NODES) {
                    float v0 = fmaxf(c[mt][nt][half * 2 + 0] + b0, 0.f);
                    float v1 = fmaxf(c[mt][nt][half * 2 + 1] + b1, 0.f);
                    if (flags & 1)
                        *(float2*)(outf + (size_t)r * 128 + col) = make_float2(v0, v1);
                    if (flags & 2) {
                        bf16 h0, l0, h1, l1;
                        bsplit(v0, h0, l0); bsplit(v1, h1, l1);
                        bf16 hh[2] = {h0, h1}, ll[2] = {l0, l1};
                        *(uint32_t*)(outh + (size_t)r * 128 + col) = *(const uint32_t*)hh;
                        *(uint32_t*)(outl + (size_t)r * 128 + col) = *(const uint32_t*)ll;
                    }
                }
            }
        }
    }
}

// ---------------- head ----------------
__global__ void k_head(const float* __restrict__ h, const float* __restrict__ Wh,
                       const float* __restrict__ bh, float* __restrict__ out)
{
    int warp = (blockIdx.x * blockDim.x + threadIdx.x) >> 5;
    int lane = threadIdx.x & 31;
    if (warp >= N_NODES) return;
    float4 hv = *(const float4*)(h + ((size_t)warp << 7) + (lane << 2));
    float p[4];
    #pragma unroll
    for (int o = 0; o < 4; o++) {
        float4 w = *(const float4*)(Wh + o * 128 + (lane << 2));
        float s = hv.x * w.x + hv.y * w.y + hv.z * w.z + hv.w * w.w;
        #pragma unroll
        for (int d = 16; d > 0; d >>= 1) s += __shfl_xor_sync(0xffffffffu, s, d);
        p[o] = s;
    }
    if (lane == 0) {
        float4 v = make_float4(p[0] + bh[0], p[1] + bh[1], p[2] + bh[2], p[3] + bh[3]);
        *(float4*)(out + (size_t)warp * 4) = v;
    }
}

// ---------------- launch ----------------
extern "C" void kernel_launch(void* const* d_in, const int* in_sizes, int n_in,
                              void* d_out, int out_size)
{
    const float* x   = (const float*)d_in[0];
    const void*  ei  = d_in[1];
    const float* Wl1 = (const float*)d_in[2];
    const float* Wr1 = (const float*)d_in[3];
    const float* b1  = (const float*)d_in[4];
    const float* Wl2 = (const float*)d_in[5];
    const float* Wr2 = (const float*)d_in[6];
    const float* b2  = (const float*)d_in[7];
    const float* Wl3 = (const float*)d_in[8];
    const float* Wr3 = (const float*)d_in[9];
    const float* b3  = (const float*)d_in[10];
    const float* Wh  = (const float*)d_in[11];
    const float* bh  = (const float*)d_in[12];
    float* out = (float*)d_out;

    float *p_agg, *p_hf;
    bf16 *p_aggh, *p_aggl, *p_h1h, *p_h1l, *p_h2h, *p_h2l, *p_Whs, *p_Wls;
    cudaGetSymbolAddress((void**)&p_agg,  g_agg);
    cudaGetSymbolAddress((void**)&p_hf,   g_hf);
    cudaGetSymbolAddress((void**)&p_aggh, g_aggh);
    cudaGetSymbolAddress((void**)&p_aggl, g_aggl);
    cudaGetSymbolAddress((void**)&p_h1h,  g_h1h);
    cudaGetSymbolAddress((void**)&p_h1l,  g_h1l);
    cudaGetSymbolAddress((void**)&p_h2h,  g_h2h);
    cudaGetSymbolAddress((void**)&p_h2l,  g_h2l);
    cudaGetSymbolAddress((void**)&p_Whs,  g_Wh);
    cudaGetSymbolAddress((void**)&p_Wls,  g_Wl);

    const int WB = (N_NODES + 7) / 8;            // warp-per-node, 256 thr
    const int GB = (N_NODES + 127) / 128;        // 391
    const int SB = (N_NODES + 1023) / 1024;      // 49
    const int CB = (N_EDGES + 1023) / 1024;      // 586
    const int MSM = 2 * STAGE_B;                 // 81920

    cudaFuncSetAttribute(k_mma_gemm, cudaFuncAttributeMaxDynamicSharedMemorySize, MSM);

    // graph structure + W split
    k_prep<<<64, 1024>>>(ei, Wl2, Wr2, Wl3, Wr3);
    k_count<<<CB, 256>>>(ei);
    k_scan1<<<SB, 1024>>>();
    k_scan23<<<SB, 1024>>>(SB);
    k_fill<<<CB, 256>>>(ei);

    const int HH = HIDDEN * HIDDEN;

    // layer 1 (FFMA, K=16) -> h1 hi/lo
    k_agg16<<<WB, 256>>>(x);
    k_sage_gemm<<<GB, 256>>>(p_agg, x, Wl1, Wr1, b1, p_h1h, p_h1l, IN_DIM);

    // layer 2 (bf16 split HMMA, pipelined) -> h2 hi/lo
    k_agg128<<<WB, 256>>>(p_h1h, p_h1l, p_aggh, p_aggl);
    k_mma_gemm<<<GB, 256, MSM>>>(p_aggh, p_aggl, p_h1h, p_h1l,
                                 p_Whs + 0 * HH, p_Wls + 0 * HH,
                                 p_Whs + 1 * HH, p_Wls + 1 * HH,
                                 b2, nullptr, p_h2h, p_h2l, 2);

    // layer 3 (bf16 split HMMA, pipelined) -> f32 for head
    k_agg128<<<WB, 256>>>(p_h2h, p_h2l, p_aggh, p_aggl);
    k_mma_gemm<<<GB, 256, MSM>>>(p_aggh, p_aggl, p_h2h, p_h2l,
                                 p_Whs + 2 * HH, p_Wls + 2 * HH,
                                 p_Whs + 3 * HH, p_Wls + 3 * HH,
                                 b3, p_hf, nullptr, nullptr, 1);

    // head
    k_head<<<WB, 256>>>(p_hf, Wh, bh, out);
}

// round 9
// speedup vs baseline: 2.3493x; 1.0674x over previous
#include <cuda_runtime.h>
#include <cuda_bf16.h>
#include <cstdint>
#include <cstddef>

#define N_NODES 50000
#define N_EDGES 600000
#define IN_DIM  16
#define HIDDEN  128
#define OUT_DIM 4

typedef __nv_bfloat16 bf16;

// ---------------- device scratch (static: no allocs allowed) ----------------
// g_deg invariant: zero at entry to every kernel_launch call (zero-init at
// module load; re-zeroed in k_fill after k_scan1 has consumed it).
__device__ int   g_deg[N_NODES];
__device__ int   g_off[N_NODES + 1];
__device__ int   g_pos[N_NODES];
__device__ int   g_csr[N_EDGES];
__device__ int   g_bsum[80];

__device__ float g_agg[(size_t)N_NODES * IN_DIM];      // layer1 agg (f32)
// bf16 hi/lo splits
__device__ bf16  g_aggh[(size_t)N_NODES * HIDDEN];
__device__ bf16  g_aggl[(size_t)N_NODES * HIDDEN];
__device__ bf16  g_h1h[(size_t)N_NODES * HIDDEN];
__device__ bf16  g_h1l[(size_t)N_NODES * HIDDEN];
__device__ bf16  g_h2h[(size_t)N_NODES * HIDDEN];
__device__ bf16  g_h2l[(size_t)N_NODES * HIDDEN];
// W splits: order Wl2, Wr2, Wl3, Wr3
__device__ bf16  g_Wh[4][HIDDEN * HIDDEN];
__device__ bf16  g_Wl[4][HIDDEN * HIDDEN];

// ---------------- helpers ----------------
__device__ __forceinline__ void bsplit(float x, bf16& h, bf16& l) {
    h = __float2bfloat16_rn(x);
    l = __float2bfloat16_rn(x - __bfloat162float(h));
}

__device__ __forceinline__ void mma_bf16(float c[4], const uint32_t a[4],
                                         uint32_t b0, uint32_t b1) {
    asm volatile(
        "mma.sync.aligned.m16n8k16.row.col.f32.bf16.bf16.f32 "
        "{%0,%1,%2,%3}, {%4,%5,%6,%7}, {%8,%9}, {%0,%1,%2,%3};"
        : "+f"(c[0]), "+f"(c[1]), "+f"(c[2]), "+f"(c[3])
        : "r"(a[0]), "r"(a[1]), "r"(a[2]), "r"(a[3]), "r"(b0), "r"(b1));
}

#define LDSM4(r, addr) \
    asm volatile("ldmatrix.sync.aligned.m8n8.x4.shared.b16 {%0,%1,%2,%3}, [%4];" \
        : "=r"((r)[0]), "=r"((r)[1]), "=r"((r)[2]), "=r"((r)[3]) : "r"(addr))
#define LDSM2(r0, r1, addr) \
    asm volatile("ldmatrix.sync.aligned.m8n8.x2.shared.b16 {%0,%1}, [%2];" \
        : "=r"(r0), "=r"(r1) : "r"(addr))
#define CP16(dst, src, sz) \
    asm volatile("cp.async.ca.shared.global [%0], [%1], 16, %2;" \
        :: "r"(dst), "l"(src), "r"(sz))
#define CP_COMMIT() asm volatile("cp.async.commit_group;")
#define CP_WAIT1()  asm volatile("cp.async.wait_group 1;")
#define CP_WAIT0()  asm volatile("cp.async.wait_group 0;")

__device__ __forceinline__ int load_idx(const void* ei, long long pos, int is32) {
    if (is32) return ((const int*)ei)[pos];
    return (int)(((const long long*)ei)[pos]);
}

// Block-local dtype detect: warp 0 scans 64 int64 slots; int32 data misread
// as int64 yields values outside [0, N_NODES) with overwhelming probability.
__device__ __forceinline__ int detect_is32(const void* ei, int tid, int* s_is32) {
    if (tid < 32) {
        const long long* p = (const long long*)ei;
        long long v0 = p[tid];
        long long v1 = p[32 + tid];
        int bad = (v0 < 0 || v0 >= N_NODES || v1 < 0 || v1 >= N_NODES) ? 1 : 0;
        unsigned m = __ballot_sync(0xffffffffu, bad);
        if (tid == 0) *s_is32 = m ? 1 : 0;
    }
    __syncthreads();
    return *s_is32;
}

// ---------------- CSR: count (+ W split folded in) ----------------
__global__ void k_count(const void* ei,
                        const float* __restrict__ Wl2, const float* __restrict__ Wr2,
                        const float* __restrict__ Wl3, const float* __restrict__ Wr3) {
    __shared__ int s_is32;
    int tid = threadIdx.x;
    int is32 = detect_is32(ei, tid, &s_is32);

    // W split: first 65536 global threads handle one element each
    int gid = blockIdx.x * 256 + tid;
    if (gid < 65536) {
        int w = gid >> 14;
        int e = gid & 16383;
        const float* src = (w == 0) ? Wl2 : (w == 1) ? Wr2 : (w == 2) ? Wl3 : Wr3;
        float v = src[e];
        bf16 h, l;
        bsplit(v, h, l);
        g_Wh[w][e] = h;
        g_Wl[w][e] = l;
    }

    int base = blockIdx.x * 1024 + tid;
    int d[4];
    #pragma unroll
    for (int k = 0; k < 4; k++) {
        int e = base + k * 256;
        d[k] = (e < N_EDGES) ? load_idx(ei, (long long)N_EDGES + e, is32) : -1;
    }
    #pragma unroll
    for (int k = 0; k < 4; k++)
        if (d[k] >= 0) atomicAdd(&g_deg[d[k]], 1);
}

// pass 1: per-block exclusive scan + block sums
__global__ void k_scan1() {
    __shared__ int warp_sums[32];
    int tid = threadIdx.x;  // 1024
    int i = blockIdx.x * 1024 + tid;
    int v = (i < N_NODES) ? g_deg[i] : 0;
    int x = v;
    #pragma unroll
    for (int d = 1; d < 32; d <<= 1) {
        int y = __shfl_up_sync(0xffffffffu, x, d);
        if ((tid & 31) >= d) x += y;
    }
    if ((tid & 31) == 31) warp_sums[tid >> 5] = x;
    __syncthreads();
    if (tid < 32) {
        int w = warp_sums[tid];
        #pragma unroll
        for (int d = 1; d < 32; d <<= 1) {
            int y = __shfl_up_sync(0xffffffffu, w, d);
            if (tid >= d) w += y;
        }
        warp_sums[tid] = w;
    }
    __syncthreads();
    int incl = x + ((tid >= 32) ? warp_sums[(tid >> 5) - 1] : 0);
    if (i < N_NODES) g_off[i] = incl - v;
    if (tid == 0) g_bsum[blockIdx.x] = warp_sums[31];
}

// pass 2+3 merged
__global__ void k_scan23(int nblk) {
    __shared__ int s_pref[64];
    int tid = threadIdx.x;  // 1024
    if (tid < 32) {
        int v0 = (tid < nblk) ? g_bsum[tid] : 0;
        int v1 = (32 + tid < nblk) ? g_bsum[32 + tid] : 0;
        int x0 = v0, x1 = v1;
        #pragma unroll
        for (int d = 1; d < 32; d <<= 1) {
            int y0 = __shfl_up_sync(0xffffffffu, x0, d);
            int y1 = __shfl_up_sync(0xffffffffu, x1, d);
            if (tid >= d) { x0 += y0; x1 += y1; }
        }
        int tot0 = __shfl_sync(0xffffffffu, x0, 31);
        s_pref[tid] = x0 - v0;
        s_pref[32 + tid] = x1 - v1 + tot0;
    }
    __syncthreads();
    int i = blockIdx.x * 1024 + tid;
    if (i < N_NODES) {
        int off = g_off[i] + s_pref[blockIdx.x];
        g_off[i] = off;
        g_pos[i] = off;
    }
    if (blockIdx.x == 0 && tid == 0) g_off[N_NODES] = N_EDGES;
}

// fill (+ re-zero g_deg for next call; scan1 already consumed it)
__global__ void k_fill(const void* ei) {
    __shared__ int s_is32;
    int tid = threadIdx.x;
    int is32 = detect_is32(ei, tid, &s_is32);

    int base = blockIdx.x * 1024 + tid;
    int s[4], d[4];
    #pragma unroll
    for (int k = 0; k < 4; k++) {
        int e = base + k * 256;
        if (e < N_EDGES) {
            s[k] = load_idx(ei, e, is32);
            d[k] = load_idx(ei, (long long)N_EDGES + e, is32);
        } else d[k] = -1;
    }
    #pragma unroll
    for (int k = 0; k < 4; k++) {
        if (d[k] >= 0) {
            int p = atomicAdd(&g_pos[d[k]], 1);
            g_csr[p] = s[k];
        }
    }
    int gid = blockIdx.x * 256 + tid;
    if (gid < N_NODES) g_deg[gid] = 0;
}

// ---------------- layer-1 aggregation (F=16, f32) ----------------
__global__ void k_agg16(const float* __restrict__ x) {
    int warp = (blockIdx.x * blockDim.x + threadIdx.x) >> 5;
    int lane = threadIdx.x & 31;
    if (warp >= N_NODES) return;
    int beg = g_off[warp], end = g_off[warp + 1];
    float acc = 0.f;
    for (int i = beg; i < end; i++) {
        int s = g_csr[i];
        if (lane < 16) acc += x[(size_t)s * IN_DIM + lane];
    }
    float inv = 1.0f / fmaxf((float)(end - beg), 1.0f);
    if (lane < 16) g_agg[(size_t)warp * IN_DIM + lane] = acc * inv;
}

// F=128 mean agg, unroll x4 for MLP
__global__ void k_agg128(const bf16* __restrict__ Hh, const bf16* __restrict__ Hl,
                         bf16* __restrict__ oh, bf16* __restrict__ ol) {
    int warp = (blockIdx.x * blockDim.x + threadIdx.x) >> 5;
    int lane = threadIdx.x & 31;
    if (warp >= N_NODES) return;
    int beg = g_off[warp], end = g_off[warp + 1];
    float a0 = 0.f, a1 = 0.f, a2 = 0.f, a3 = 0.f;
    int loff = lane << 2;
    int i = beg;
    for (; i + 4 <= end; i += 4) {
        int s0 = g_csr[i], s1 = g_csr[i + 1], s2 = g_csr[i + 2], s3 = g_csr[i + 3];
        uint2 h0 = *(const uint2*)(Hh + ((size_t)s0 << 7) + loff);
        uint2 l0 = *(const uint2*)(Hl + ((size_t)s0 << 7) + loff);
        uint2 h1 = *(const uint2*)(Hh + ((size_t)s1 << 7) + loff);
        uint2 l1 = *(const uint2*)(Hl + ((size_t)s1 << 7) + loff);
        uint2 h2 = *(const uint2*)(Hh + ((size_t)s2 << 7) + loff);
        uint2 l2 = *(const uint2*)(Hl + ((size_t)s2 << 7) + loff);
        uint2 h3 = *(const uint2*)(Hh + ((size_t)s3 << 7) + loff);
        uint2 l3 = *(const uint2*)(Hl + ((size_t)s3 << 7) + loff);
        float2 f;
        f = __bfloat1622float2(*(__nv_bfloat162*)&h0.x); a0 += f.x; a1 += f.y;
        f = __bfloat1622float2(*(__nv_bfloat162*)&h0.y); a2 += f.x; a3 += f.y;
        f = __bfloat1622float2(*(__nv_bfloat162*)&l0.x); a0 += f.x; a1 += f.y;
        f = __bfloat1622float2(*(__nv_bfloat162*)&l0.y); a2 += f.x; a3 += f.y;
        f = __bfloat1622float2(*(__nv_bfloat162*)&h1.x); a0 += f.x; a1 += f.y;
        f = __bfloat1622float2(*(__nv_bfloat162*)&h1.y); a2 += f.x; a3 += f.y;
        f = __bfloat1622float2(*(__nv_bfloat162*)&l1.x); a0 += f.x; a1 += f.y;
        f = __bfloat1622float2(*(__nv_bfloat162*)&l1.y); a2 += f.x; a3 += f.y;
        f = __bfloat1622float2(*(__nv_bfloat162*)&h2.x); a0 += f.x; a1 += f.y;
        f = __bfloat1622float2(*(__nv_bfloat162*)&h2.y); a2 += f.x; a3 += f.y;
        f = __bfloat1622float2(*(__nv_bfloat162*)&l2.x); a0 += f.x; a1 += f.y;
        f = __bfloat1622float2(*(__nv_bfloat162*)&l2.y); a2 += f.x; a3 += f.y;
        f = __bfloat1622float2(*(__nv_bfloat162*)&h3.x); a0 += f.x; a1 += f.y;
        f = __bfloat1622float2(*(__nv_bfloat162*)&h3.y); a2 += f.x; a3 += f.y;
        f = __bfloat1622float2(*(__nv_bfloat162*)&l3.x); a0 += f.x; a1 += f.y;
        f = __bfloat1622float2(*(__nv_bfloat162*)&l3.y); a2 += f.x; a3 += f.y;
    }
    for (; i < end; i++) {
        int s = g_csr[i];
        uint2 uh = *(const uint2*)(Hh + ((size_t)s << 7) + loff);
        uint2 ul = *(const uint2*)(Hl + ((size_t)s << 7) + loff);
        float2 f;
        f = __bfloat1622float2(*(__nv_bfloat162*)&uh.x); a0 += f.x; a1 += f.y;
        f = __bfloat1622float2(*(__nv_bfloat162*)&uh.y); a2 += f.x; a3 += f.y;
        f = __bfloat1622float2(*(__nv_bfloat162*)&ul.x); a0 += f.x; a1 += f.y;
        f = __bfloat1622float2(*(__nv_bfloat162*)&ul.y); a2 += f.x; a3 += f.y;
    }
    float inv = 1.0f / fmaxf((float)(end - beg), 1.0f);
    bf16 vh[4], vl[4];
    bsplit(a0 * inv, vh[0], vl[0]);
    bsplit(a1 * inv, vh[1], vl[1]);
    bsplit(a2 * inv, vh[2], vl[2]);
    bsplit(a3 * inv, vh[3], vl[3]);
    size_t o = ((size_t)warp << 7) + loff;
    *(uint2*)(oh + o) = *(const uint2*)vh;
    *(uint2*)(ol + o) = *(const uint2*)vl;
}

// ---------------- layer-1 FFMA GEMM (K=16 per segment), hi/lo out ----------
__global__ __launch_bounds__(256)
void k_sage_gemm(const float* __restrict__ A1, const float* __restrict__ A2,
                 const float* __restrict__ W1, const float* __restrict__ W2,
                 const float* __restrict__ bias,
                 bf16* __restrict__ out_hi, bf16* __restrict__ out_lo,
                 int K)
{
    __shared__ float As[16][128];
    __shared__ float Ws[16][128];
    int tid = threadIdx.x;
    int tx = tid & 15;
    int ty = tid >> 4;
    int row0 = blockIdx.x * 128;

    float c[8][8];
    #pragma unroll
    for (int i = 0; i < 8; i++)
        #pragma unroll
        for (int j = 0; j < 8; j++) c[i][j] = 0.f;

    #pragma unroll
    for (int seg = 0; seg < 2; seg++) {
        const float* A = seg ? A2 : A1;
        const float* W = seg ? W2 : W1;
        for (int kk = 0; kk < K; kk += 16) {
            #pragma unroll
            for (int t = 0; t < 2; t++) {
                int idx = tid + t * 256;
                int m  = idx >> 2;
                int kq = idx & 3;
                int gm = row0 + m;
                float4 v = make_float4(0.f, 0.f, 0.f, 0.f);
                if (gm < N_NODES)
                    v = *(const float4*)(A + (size_t)gm * K + kk + kq * 4);
                As[kq * 4 + 0][m] = v.x; As[kq * 4 + 1][m] = v.y;
                As[kq * 4 + 2][m] = v.z; As[kq * 4 + 3][m] = v.w;
                float4 w = *(const float4*)(W + (size_t)m * K + kk + kq * 4);
                Ws[kq * 4 + 0][m] = w.x; Ws[kq * 4 + 1][m] = w.y;
                Ws[kq * 4 + 2][m] = w.z; Ws[kq * 4 + 3][m] = w.w;
            }
            __syncthreads();
            #pragma unroll
            for (int k = 0; k < 16; k++) {
                float a[8], w[8];
                *(float4*)&a[0] = *(const float4*)&As[k][ty * 8];
                *(float4*)&a[4] = *(const float4*)&As[k][ty * 8 + 4];
                *(float4*)&w[0] = *(const float4*)&Ws[k][tx * 8];
                *(float4*)&w[4] = *(const float4*)&Ws[k][tx * 8 + 4];
                #pragma unroll
                for (int i = 0; i < 8; i++)
                    #pragma unroll
                    for (int j = 0; j < 8; j++)
                        c[i][j] += a[i] * w[j];
            }
            __syncthreads();
        }
    }

    #pragma unroll
    for (int i = 0; i < 8; i++) {
        int gm = row0 + ty * 8 + i;
        if (gm >= N_NODES) continue;
        #pragma unroll
        for (int j = 0; j < 8; j += 4) {
            int gn = tx * 8 + j;
            bf16 vh[4], vl[4];
            #pragma unroll
            for (int q = 0; q < 4; q++) {
                float v = fmaxf(c[i][j + q] + bias[gn + q], 0.f);
                bsplit(v, vh[q], vl[q]);
            }
            *(uint2*)(out_hi + (size_t)gm * 128 + gn) = *(const uint2*)vh;
            *(uint2*)(out_lo + (size_t)gm * 128 + gn) = *(const uint2*)vl;
        }
    }
}

// ---------------- bf16 split-HMMA GEMM, cp.async pipelined + ldmatrix -------
// out[M,128] = relu([A1|A2](M,256) @ [B1|B2](128,256)^T + bias)
// mode 0: write bf16 hi/lo activations.  mode 1: fused head -> outd[M,4].
#define TSTRIDE 80          // bytes per smem row
#define TILE_AL 10240
#define TILE_WH 20480
#define TILE_WL 30720
#define STAGE_B 40960

__global__ __launch_bounds__(256, 2)
void k_mma_gemm(const bf16* __restrict__ A1h, const bf16* __restrict__ A1l,
                const bf16* __restrict__ A2h, const bf16* __restrict__ A2l,
                const bf16* __restrict__ B1h, const bf16* __restrict__ B1l,
                const bf16* __restrict__ B2h, const bf16* __restrict__ B2l,
                const float* __restrict__ bias,
                bf16* __restrict__ outh, bf16* __restrict__ outl,
                const float* __restrict__ Whd, const float* __restrict__ bhd,
                float* __restrict__ outd,
                int mode)
{
    extern __shared__ char sm[];
    uint32_t smb = (uint32_t)__cvta_generic_to_shared(sm);

    int tid = threadIdx.x;
    int wid = tid >> 5;
    int lane = tid & 31;
    int warp_m = wid & 3;
    int warp_n = wid >> 2;
    int row0 = blockIdx.x * 128;

    int g = lane >> 3;
    uint32_t aoff = (uint32_t)(((lane & 7) + ((g & 1) << 3)) * TSTRIDE + (g >> 1) * 16);
    uint32_t boff = (uint32_t)((lane & 7) * TSTRIDE + ((lane >> 3) & 1) * 16);

    int lm = (tid >> 2);
    int lq = (tid & 3);
    uint32_t dof0 = (uint32_t)(lm * TSTRIDE + lq * 16);
    uint32_t dof1 = (uint32_t)((lm + 64) * TSTRIDE + lq * 16);

    float c[2][8][4];
    #pragma unroll
    for (int mt = 0; mt < 2; mt++)
        #pragma unroll
        for (int nt = 0; nt < 8; nt++)
            #pragma unroll
            for (int q = 0; q < 4; q++) c[mt][nt][q] = 0.f;

    auto load_chunk = [&](int ch, int stage) {
        int seg = ch >> 2;
        int k0 = (ch & 3) * 32;
        const bf16* Ah = seg ? A2h : A1h;
        const bf16* Al = seg ? A2l : A1l;
        const bf16* Bh = seg ? B2h : B1h;
        const bf16* Bl = seg ? B2l : B1l;
        uint32_t SB = smb + stage * STAGE_B;
        #pragma unroll
        for (int t = 0; t < 2; t++) {
            int m = (t == 0) ? lm : lm + 64;
            uint32_t dof = (t == 0) ? dof0 : dof1;
            int gm = row0 + m;
            uint32_t sz = (gm < N_NODES) ? 16u : 0u;
            size_t gmc = (gm < N_NODES) ? (size_t)gm : 0;
            CP16(SB + dof,           Ah + (gmc << 7) + k0 + lq * 8, sz);
            CP16(SB + TILE_AL + dof, Al + (gmc << 7) + k0 + lq * 8, sz);
            CP16(SB + TILE_WH + dof, Bh + ((size_t)m << 7) + k0 + lq * 8, 16u);
            CP16(SB + TILE_WL + dof, Bl + ((size_t)m << 7) + k0 + lq * 8, 16u);
        }
    };

    load_chunk(0, 0);
    CP_COMMIT();

    for (int ch = 0; ch < 8; ch++) {
        if (ch < 7) {
            load_chunk(ch + 1, (ch + 1) & 1);
            CP_COMMIT();
            CP_WAIT1();
        } else {
            CP_WAIT0();
        }
        __syncthreads();

        uint32_t SB = smb + (ch & 1) * STAGE_B;
        #pragma unroll
        for (int ks = 0; ks < 2; ks++) {
            uint32_t kso = (uint32_t)(ks * 32);
            uint32_t ah[2][4], al[2][4];
            #pragma unroll
            for (int mt = 0; mt < 2; mt++) {
                uint32_t abase = SB + (uint32_t)((warp_m * 32 + mt * 16) * TSTRIDE) + kso + aoff;
                LDSM4(ah[mt], abase);
                LDSM4(al[mt], abase + TILE_AL);
            }
            #pragma unroll
            for (int nt = 0; nt < 8; nt++) {
                uint32_t bbase = SB + TILE_WH + (uint32_t)((warp_n * 64 + nt * 8) * TSTRIDE) + kso + boff;
                uint32_t bh0, bh1, bl0, bl1;
                LDSM2(bh0, bh1, bbase);
                LDSM2(bl0, bl1, bbase + (TILE_WL - TILE_WH));
                #pragma unroll
                for (int mt = 0; mt < 2; mt++) {
                    mma_bf16(c[mt][nt], ah[mt], bh0, bh1);
                    mma_bf16(c[mt][nt], ah[mt], bl0, bl1);
                    mma_bf16(c[mt][nt], al[mt], bh0, bh1);
                }
            }
        }
        __syncthreads();
    }

    int tg = lane & 3;
    int gp = lane >> 2;

    if (mode == 0) {
        // write bf16 hi/lo activations
        #pragma unroll
        for (int mt = 0; mt < 2; mt++) {
            int row = row0 + warp_m * 32 + mt * 16 + gp;
            #pragma unroll
            for (int nt = 0; nt < 8; nt++) {
                int col = warp_n * 64 + nt * 8 + 2 * tg;
                float b0 = bias[col], b1 = bias[col + 1];
                #pragma unroll
                for (int half = 0; half < 2; half++) {
                    int r = row + half * 8;
                    if (r < N_NODES) {
                        float v0 = fmaxf(c[mt][nt][half * 2 + 0] + b0, 0.f);
                        float v1 = fmaxf(c[mt][nt][half * 2 + 1] + b1, 0.f);
                        bf16 h0, l0, h1, l1;
                        bsplit(v0, h0, l0); bsplit(v1, h1, l1);
                        bf16 hh[2] = {h0, h1}, ll[2] = {l0, l1};
                        *(uint32_t*)(outh + (size_t)r * 128 + col) = *(const uint32_t*)hh;
                        *(uint32_t*)(outl + (size_t)r * 128 + col) = *(const uint32_t*)ll;
                    }
                }
            }
        }
    } else {
        // fused head: out[r, 0..3] = relu(h3[r,:]) @ Wh^T + bh
        float p[4][4];
        #pragma unroll
        for (int i = 0; i < 4; i++)
            #pragma unroll
            for (int o = 0; o < 4; o++) p[i][o] = 0.f;

        #pragma unroll
        for (int mt = 0; mt < 2; mt++) {
            #pragma unroll
            for (int nt = 0; nt < 8; nt++) {
                int col = warp_n * 64 + nt * 8 + 2 * tg;
                float b0 = bias[col], b1 = bias[col + 1];
                #pragma unroll
                for (int half = 0; half < 2; half++) {
                    float v0 = fmaxf(c[mt][nt][half * 2 + 0] + b0, 0.f);
                    float v1 = fmaxf(c[mt][nt][half * 2 + 1] + b1, 0.f);
                    #pragma unroll
                    for (int o = 0; o < 4; o++) {
                        p[mt * 2 + half][o] += v0 * Whd[o * 128 + col]
                                             + v1 * Whd[o * 128 + col + 1];
                    }
                }
            }
        }
        // reduce over tg (lane bits 0..1)
        #pragma unroll
        for (int i = 0; i < 4; i++)
            #pragma unroll
            for (int o = 0; o < 4; o++) {
                float v = p[i][o];
                v += __shfl_xor_sync(0xffffffffu, v, 1);
                v += __shfl_xor_sync(0xffffffffu, v, 2);
                p[i][o] = v;
            }
        float* sred = (float*)sm;   // [128][8]: [row_local][warp_n*4 + o]
        if (tg == 0) {
            #pragma unroll
            for (int mt = 0; mt < 2; mt++)
                #pragma unroll
                for (int half = 0; half < 2; half++) {
                    int rl = warp_m * 32 + mt * 16 + half * 8 + gp;
                    #pragma unroll
                    for (int o = 0; o < 4; o++)
                        sred[rl * 8 + warp_n * 4 + o] = p[mt * 2 + half][o];
                }
        }
        __syncthreads();
        for (int t = tid; t < 512; t += 256) {
            int rl = t >> 2, o = t & 3;
            int r = row0 + rl;
            if (r < N_NODES)
                outd[(size_t)r * 4 + o] = sred[rl * 8 + o] + sred[rl * 8 + 4 + o] + bhd[o];
        }
    }
}

// ---------------- launch ----------------
extern "C" void kernel_launch(void* const* d_in, const int* in_sizes, int n_in,
                              void* d_out, int out_size)
{
    const float* x   = (const float*)d_in[0];
    const void*  ei  = d_in[1];
    const float* Wl1 = (const float*)d_in[2];
    const float* Wr1 = (const float*)d_in[3];
    const float* b1  = (const float*)d_in[4];
    const float* Wl2 = (const float*)d_in[5];
    const float* Wr2 = (const float*)d_in[6];
    const float* b2  = (const float*)d_in[7];
    const float* Wl3 = (const float*)d_in[8];
    const float* Wr3 = (const float*)d_in[9];
    const float* b3  = (const float*)d_in[10];
    const float* Wh  = (const float*)d_in[11];
    const float* bh  = (const float*)d_in[12];
    float* out = (float*)d_out;

    float *p_agg;
    bf16 *p_aggh, *p_aggl, *p_h1h, *p_h1l, *p_h2h, *p_h2l, *p_Whs, *p_Wls;
    cudaGetSymbolAddress((void**)&p_agg,  g_agg);
    cudaGetSymbolAddress((void**)&p_aggh, g_aggh);
    cudaGetSymbolAddress((void**)&p_aggl, g_aggl);
    cudaGetSymbolAddress((void**)&p_h1h,  g_h1h);
    cudaGetSymbolAddress((void**)&p_h1l,  g_h1l);
    cudaGetSymbolAddress((void**)&p_h2h,  g_h2h);
    cudaGetSymbolAddress((void**)&p_h2l,  g_h2l);
    cudaGetSymbolAddress((void**)&p_Whs,  g_Wh);
    cudaGetSymbolAddress((void**)&p_Wls,  g_Wl);

    const int WB = (N_NODES + 7) / 8;            // warp-per-node, 256 thr
    const int GB = (N_NODES + 127) / 128;        // 391
    const int SB = (N_NODES + 1023) / 1024;      // 49
    const int CB = (N_EDGES + 1023) / 1024;      // 586
    const int MSM = 2 * STAGE_B;                 // 81920

    cudaFuncSetAttribute(k_mma_gemm, cudaFuncAttributeMaxDynamicSharedMemorySize, MSM);

    // graph structure (+ W split inside k_count; g_deg pre-zeroed invariant)
    k_count<<<CB, 256>>>(ei, Wl2, Wr2, Wl3, Wr3);
    k_scan1<<<SB, 1024>>>();
    k_scan23<<<SB, 1024>>>(SB);
    k_fill<<<CB, 256>>>(ei);

    const int HH = HIDDEN * HIDDEN;

    // layer 1 (FFMA, K=16) -> h1 hi/lo
    k_agg16<<<WB, 256>>>(x);
    k_sage_gemm<<<GB, 256>>>(p_agg, x, Wl1, Wr1, b1, p_h1h, p_h1l, IN_DIM);

    // layer 2 (bf16 split HMMA, pipelined) -> h2 hi/lo
    k_agg128<<<WB, 256>>>(p_h1h, p_h1l, p_aggh, p_aggl);
    k_mma_gemm<<<GB, 256, MSM>>>(p_aggh, p_aggl, p_h1h, p_h1l,
                                 p_Whs + 0 * HH, p_Wls + 0 * HH,
                                 p_Whs + 1 * HH, p_Wls + 1 * HH,
                                 b2, p_h2h, p_h2l, nullptr, nullptr, nullptr, 0);

    // layer 3 (bf16 split HMMA, pipelined) + fused head -> out
    k_agg128<<<WB, 256>>>(p_h2h, p_h2l, p_aggh, p_aggl);
    k_mma_gemm<<<GB, 256, MSM>>>(p_aggh, p_aggl, p_h2h, p_h2l,
                                 p_Whs + 2 * HH, p_Wls + 2 * HH,
                                 p_Whs + 3 * HH, p_Wls + 3 * HH,
                                 b3, nullptr, nullptr, Wh, bh, out, 1);
}

// round 10
// speedup vs baseline: 2.6024x; 1.1077x over previous
#include <cuda_runtime.h>
#include <cuda_fp16.h>
#include <cstdint>
#include <cstddef>

#define N_NODES 50000
#define N_EDGES 600000
#define IN_DIM  16
#define HIDDEN  128
#define OUT_DIM 4

typedef __half f16;

// ---------------- device scratch (static: no allocs allowed) ----------------
// Invariants at entry to every kernel_launch call (zero-init at module load;
// re-zeroed in k_fill after consumption): g_deg == 0, g_state == 0.
__device__ int      g_deg[N_NODES];
__device__ unsigned g_state[64];
__device__ int      g_off[N_NODES + 1];
__device__ int      g_pos[N_NODES];
__device__ int      g_csr[N_EDGES];

__device__ float g_agg[(size_t)N_NODES * IN_DIM];      // layer1 agg (f32)
// fp16 hi/lo splits
__device__ f16   g_aggh[(size_t)N_NODES * HIDDEN];
__device__ f16   g_aggl[(size_t)N_NODES * HIDDEN];
__device__ f16   g_h1h[(size_t)N_NODES * HIDDEN];
__device__ f16   g_h1l[(size_t)N_NODES * HIDDEN];
__device__ f16   g_h2h[(size_t)N_NODES * HIDDEN];
__device__ f16   g_h2l[(size_t)N_NODES * HIDDEN];
// W splits: order Wl2, Wr2, Wl3, Wr3
__device__ f16   g_Wh[4][HIDDEN * HIDDEN];
__device__ f16   g_Wl[4][HIDDEN * HIDDEN];

// ---------------- helpers ----------------
__device__ __forceinline__ void hsplit(float x, f16& h, f16& l) {
    h = __float2half_rn(x);
    l = __float2half_rn(x - __half2float(h));
}

__device__ __forceinline__ void mma_f16(float c[4], const uint32_t a[4],
                                        uint32_t b0, uint32_t b1) {
    asm volatile(
        "mma.sync.aligned.m16n8k16.row.col.f32.f16.f16.f32 "
        "{%0,%1,%2,%3}, {%4,%5,%6,%7}, {%8,%9}, {%0,%1,%2,%3};"
        : "+f"(c[0]), "+f"(c[1]), "+f"(c[2]), "+f"(c[3])
        : "r"(a[0]), "r"(a[1]), "r"(a[2]), "r"(a[3]), "r"(b0), "r"(b1));
}

#define LDSM4(r, addr) \
    asm volatile("ldmatrix.sync.aligned.m8n8.x4.shared.b16 {%0,%1,%2,%3}, [%4];" \
        : "=r"((r)[0]), "=r"((r)[1]), "=r"((r)[2]), "=r"((r)[3]) : "r"(addr))
#define LDSM2(r0, r1, addr) \
    asm volatile("ldmatrix.sync.aligned.m8n8.x2.shared.b16 {%0,%1}, [%2];" \
        : "=r"(r0), "=r"(r1) : "r"(addr))
#define CP16(dst, src, sz) \
    asm volatile("cp.async.ca.shared.global [%0], [%1], 16, %2;" \
        :: "r"(dst), "l"(src), "r"(sz))
#define CP_COMMIT() asm volatile("cp.async.commit_group;")
#define CP_WAIT1()  asm volatile("cp.async.wait_group 1;")
#define CP_WAIT0()  asm volatile("cp.async.wait_group 0;")

__device__ __forceinline__ int load_idx(const void* ei, long long pos, int is32) {
    if (is32) return ((const int*)ei)[pos];
    return (int)(((const long long*)ei)[pos]);
}

// Block-local dtype detect: warp 0 scans 64 int64 slots; int32 data misread
// as int64 yields values outside [0, N_NODES) with overwhelming probability.
__device__ __forceinline__ int detect_is32(const void* ei, int tid, int* s_is32) {
    if (tid < 32) {
        const long long* p = (const long long*)ei;
        long long v0 = p[tid];
        long long v1 = p[32 + tid];
        int bad = (v0 < 0 || v0 >= N_NODES || v1 < 0 || v1 >= N_NODES) ? 1 : 0;
        unsigned m = __ballot_sync(0xffffffffu, bad);
        if (tid == 0) *s_is32 = m ? 1 : 0;
    }
    __syncthreads();
    return *s_is32;
}

// ---------------- CSR: count (+ W split folded in), 8 edges/thread ---------
__global__ void k_count(const void* ei,
                        const float* __restrict__ Wl2, const float* __restrict__ Wr2,
                        const float* __restrict__ Wl3, const float* __restrict__ Wr3) {
    __shared__ int s_is32;
    int tid = threadIdx.x;
    int is32 = detect_is32(ei, tid, &s_is32);

    // W split: first 65536 global threads handle one element each
    int gid = blockIdx.x * 256 + tid;
    if (gid < 65536) {
        int w = gid >> 14;
        int e = gid & 16383;
        const float* src = (w == 0) ? Wl2 : (w == 1) ? Wr2 : (w == 2) ? Wl3 : Wr3;
        float v = src[e];
        f16 h, l;
        hsplit(v, h, l);
        g_Wh[w][e] = h;
        g_Wl[w][e] = l;
    }

    int base = blockIdx.x * 2048 + tid;
    int d[8];
    #pragma unroll
    for (int k = 0; k < 8; k++) {
        int e = base + k * 256;
        d[k] = (e < N_EDGES) ? load_idx(ei, (long long)N_EDGES + e, is32) : -1;
    }
    #pragma unroll
    for (int k = 0; k < 8; k++)
        if (d[k] >= 0) atomicAdd(&g_deg[d[k]], 1);
}

// ---------------- single-pass scan with decoupled lookback ----------------
// 49 blocks x 1024; all co-resident in wave 1. g_state[b]: flag(2b)|value.
__global__ void k_scan() {
    __shared__ int warp_sums[32];
    __shared__ int s_prev;
    int tid = threadIdx.x;  // 1024
    int bid = blockIdx.x;
    int i = bid * 1024 + tid;
    int v = (i < N_NODES) ? g_deg[i] : 0;
    int x = v;
    #pragma unroll
    for (int d = 1; d < 32; d <<= 1) {
        int y = __shfl_up_sync(0xffffffffu, x, d);
        if ((tid & 31) >= d) x += y;
    }
    if ((tid & 31) == 31) warp_sums[tid >> 5] = x;
    __syncthreads();
    if (tid < 32) {
        int w = warp_sums[tid];
        #pragma unroll
        for (int d = 1; d < 32; d <<= 1) {
            int y = __shfl_up_sync(0xffffffffu, w, d);
            if (tid >= d) w += y;
        }
        warp_sums[tid] = w;
    }
    __syncthreads();
    int excl = x - v + ((tid >= 32) ? warp_sums[(tid >> 5) - 1] : 0);
    int block_total = warp_sums[31];

    if (tid == 0) {
        if (bid == 0) {
            *(volatile unsigned*)&g_state[0] = (2u << 30) | (unsigned)block_total;
            s_prev = 0;
        } else {
            *(volatile unsigned*)&g_state[bid] = (1u << 30) | (unsigned)block_total;
            int sum = 0;
            for (int p = bid - 1; p >= 0; ) {
                unsigned s;
                do { s = *(volatile unsigned*)&g_state[p]; } while ((s >> 30) == 0u);
                sum += (int)(s & 0x3FFFFFFFu);
                if ((s >> 30) == 2u) break;
                --p;
            }
            *(volatile unsigned*)&g_state[bid] = (2u << 30) | (unsigned)(sum + block_total);
            s_prev = sum;
        }
    }
    __syncthreads();
    if (i < N_NODES) {
        int off = excl + s_prev;
        g_off[i] = off;
        g_pos[i] = off;
    }
    if (bid == 0 && tid == 0) g_off[N_NODES] = N_EDGES;
}

// fill, 8 edges/thread (+ re-zero g_deg, g_state for next call)
__global__ void k_fill(const void* ei) {
    __shared__ int s_is32;
    int tid = threadIdx.x;
    int is32 = detect_is32(ei, tid, &s_is32);

    int base = blockIdx.x * 2048 + tid;
    int s[8], d[8];
    #pragma unroll
    for (int k = 0; k < 8; k++) {
        int e = base + k * 256;
        if (e < N_EDGES) {
            s[k] = load_idx(ei, e, is32);
            d[k] = load_idx(ei, (long long)N_EDGES + e, is32);
        } else d[k] = -1;
    }
    #pragma unroll
    for (int k = 0; k < 8; k++) {
        if (d[k] >= 0) {
            int p = atomicAdd(&g_pos[d[k]], 1);
            g_csr[p] = s[k];
        }
    }
    int gid = blockIdx.x * 256 + tid;
    if (gid < N_NODES) g_deg[gid] = 0;
    if (gid < 64) g_state[gid] = 0u;
}

// ---------------- layer-1 aggregation (F=16, f32) ----------------
__global__ void k_agg16(const float* __restrict__ x) {
    int warp = (blockIdx.x * blockDim.x + threadIdx.x) >> 5;
    int lane = threadIdx.x & 31;
    if (warp >= N_NODES) return;
    int beg = g_off[warp], end = g_off[warp + 1];
    float acc = 0.f;
    for (int i = beg; i < end; i++) {
        int s = g_csr[i];
        if (lane < 16) acc += x[(size_t)s * IN_DIM + lane];
    }
    float inv = 1.0f / fmaxf((float)(end - beg), 1.0f);
    if (lane < 16) g_agg[(size_t)warp * IN_DIM + lane] = acc * inv;
}

// F=128 mean agg: reads ONLY the fp16 hi activations (256B/edge), f32 acc,
// writes fp16 hi/lo mean. Unroll x8 / x4 / x1 for MLP.
__global__ void k_agg128(const f16* __restrict__ Hh,
                         f16* __restrict__ oh, f16* __restrict__ ol) {
    int warp = (blockIdx.x * blockDim.x + threadIdx.x) >> 5;
    int lane = threadIdx.x & 31;
    if (warp >= N_NODES) return;
    int beg = g_off[warp], end = g_off[warp + 1];
    float a0 = 0.f, a1 = 0.f, a2 = 0.f, a3 = 0.f;
    int loff = lane << 2;
    int i = beg;
    for (; i + 8 <= end; i += 8) {
        uint2 u[8];
        #pragma unroll
        for (int k = 0; k < 8; k++) {
            int s = g_csr[i + k];
            u[k] = *(const uint2*)(Hh + ((size_t)s << 7) + loff);
        }
        #pragma unroll
        for (int k = 0; k < 8; k++) {
            float2 f;
            f = __half22float2(*(__half2*)&u[k].x); a0 += f.x; a1 += f.y;
            f = __half22float2(*(__half2*)&u[k].y); a2 += f.x; a3 += f.y;
        }
    }
    for (; i + 4 <= end; i += 4) {
        uint2 u[4];
        #pragma unroll
        for (int k = 0; k < 4; k++) {
            int s = g_csr[i + k];
            u[k] = *(const uint2*)(Hh + ((size_t)s << 7) + loff);
        }
        #pragma unroll
        for (int k = 0; k < 4; k++) {
            float2 f;
            f = __half22float2(*(__half2*)&u[k].x); a0 += f.x; a1 += f.y;
            f = __half22float2(*(__half2*)&u[k].y); a2 += f.x; a3 += f.y;
        }
    }
    for (; i < end; i++) {
        int s = g_csr[i];
        uint2 u = *(const uint2*)(Hh + ((size_t)s << 7) + loff);
        float2 f;
        f = __half22float2(*(__half2*)&u.x); a0 += f.x; a1 += f.y;
        f = __half22float2(*(__half2*)&u.y); a2 += f.x; a3 += f.y;
    }
    float inv = 1.0f / fmaxf((float)(end - beg), 1.0f);
    f16 vh[4], vl[4];
    hsplit(a0 * inv, vh[0], vl[0]);
    hsplit(a1 * inv, vh[1], vl[1]);
    hsplit(a2 * inv, vh[2], vl[2]);
    hsplit(a3 * inv, vh[3], vl[3]);
    size_t o = ((size_t)warp << 7) + loff;
    *(uint2*)(oh + o) = *(const uint2*)vh;
    *(uint2*)(ol + o) = *(const uint2*)vl;
}

// ---------------- layer-1 FFMA GEMM (K=16 per segment), fp16 hi/lo out -----
__global__ __launch_bounds__(256)
void k_sage_gemm(const float* __restrict__ A1, const float* __restrict__ A2,
                 const float* __restrict__ W1, const float* __restrict__ W2,
                 const float* __restrict__ bias,
                 f16* __restrict__ out_hi, f16* __restrict__ out_lo,
                 int K)
{
    __shared__ float As[16][128];
    __shared__ float Ws[16][128];
    int tid = threadIdx.x;
    int tx = tid & 15;
    int ty = tid >> 4;
    int row0 = blockIdx.x * 128;

    float c[8][8];
    #pragma unroll
    for (int i = 0; i < 8; i++)
        #pragma unroll
        for (int j = 0; j < 8; j++) c[i][j] = 0.f;

    #pragma unroll
    for (int seg = 0; seg < 2; seg++) {
        const float* A = seg ? A2 : A1;
        const float* W = seg ? W2 : W1;
        for (int kk = 0; kk < K; kk += 16) {
            #pragma unroll
            for (int t = 0; t < 2; t++) {
                int idx = tid + t * 256;
                int m  = idx >> 2;
                int kq = idx & 3;
                int gm = row0 + m;
                float4 v = make_float4(0.f, 0.f, 0.f, 0.f);
                if (gm < N_NODES)
                    v = *(const float4*)(A + (size_t)gm * K + kk + kq * 4);
                As[kq * 4 + 0][m] = v.x; As[kq * 4 + 1][m] = v.y;
                As[kq * 4 + 2][m] = v.z; As[kq * 4 + 3][m] = v.w;
                float4 w = *(const float4*)(W + (size_t)m * K + kk + kq * 4);
                Ws[kq * 4 + 0][m] = w.x; Ws[kq * 4 + 1][m] = w.y;
                Ws[kq * 4 + 2][m] = w.z; Ws[kq * 4 + 3][m] = w.w;
            }
            __syncthreads();
            #pragma unroll
            for (int k = 0; k < 16; k++) {
                float a[8], w[8];
                *(float4*)&a[0] = *(const float4*)&As[k][ty * 8];
                *(float4*)&a[4] = *(const float4*)&As[k][ty * 8 + 4];
                *(float4*)&w[0] = *(const float4*)&Ws[k][tx * 8];
                *(float4*)&w[4] = *(const float4*)&Ws[k][tx * 8 + 4];
                #pragma unroll
                for (int i = 0; i < 8; i++)
                    #pragma unroll
                    for (int j = 0; j < 8; j++)
                        c[i][j] += a[i] * w[j];
            }
            __syncthreads();
        }
    }

    #pragma unroll
    for (int i = 0; i < 8; i++) {
        int gm = row0 + ty * 8 + i;
        if (gm >= N_NODES) continue;
        #pragma unroll
        for (int j = 0; j < 8; j += 4) {
            int gn = tx * 8 + j;
            f16 vh[4], vl[4];
            #pragma unroll
            for (int q = 0; q < 4; q++) {
                float v = fmaxf(c[i][j + q] + bias[gn + q], 0.f);
                hsplit(v, vh[q], vl[q]);
            }
            *(uint2*)(out_hi + (size_t)gm * 128 + gn) = *(const uint2*)vh;
            *(uint2*)(out_lo + (size_t)gm * 128 + gn) = *(const uint2*)vl;
        }
    }
}

// ---------------- fp16 split-HMMA GEMM, cp.async pipelined + ldmatrix -------
// out[M,128] = relu([A1|A2](M,256) @ [B1|B2](128,256)^T + bias)
// mode 0: write fp16 hi/lo activations.  mode 1: fused head -> outd[M,4].
#define TSTRIDE 80          // bytes per smem row
#define TILE_AL 10240
#define TILE_WH 20480
#define TILE_WL 30720
#define STAGE_B 40960

__global__ __launch_bounds__(256, 2)
void k_mma_gemm(const f16* __restrict__ A1h, const f16* __restrict__ A1l,
                const f16* __restrict__ A2h, const f16* __restrict__ A2l,
                const f16* __restrict__ B1h, const f16* __restrict__ B1l,
                const f16* __restrict__ B2h, const f16* __restrict__ B2l,
                const float* __restrict__ bias,
                f16* __restrict__ outh, f16* __restrict__ outl,
                const float* __restrict__ Whd, const float* __restrict__ bhd,
                float* __restrict__ outd,
                int mode)
{
    extern __shared__ char sm[];
    uint32_t smb = (uint32_t)__cvta_generic_to_shared(sm);

    int tid = threadIdx.x;
    int wid = tid >> 5;
    int lane = tid & 31;
    int warp_m = wid & 3;
    int warp_n = wid >> 2;
    int row0 = blockIdx.x * 128;

    int g = lane >> 3;
    uint32_t aoff = (uint32_t)(((lane & 7) + ((g & 1) << 3)) * TSTRIDE + (g >> 1) * 16);
    uint32_t boff = (uint32_t)((lane & 7) * TSTRIDE + ((lane >> 3) & 1) * 16);

    int lm = (tid >> 2);
    int lq = (tid & 3);
    uint32_t dof0 = (uint32_t)(lm * TSTRIDE + lq * 16);
    uint32_t dof1 = (uint32_t)((lm + 64) * TSTRIDE + lq * 16);

    float c[2][8][4];
    #pragma unroll
    for (int mt = 0; mt < 2; mt++)
        #pragma unroll
        for (int nt = 0; nt < 8; nt++)
            #pragma unroll
            for (int q = 0; q < 4; q++) c[mt][nt][q] = 0.f;

    auto load_chunk = [&](int ch, int stage) {
        int seg = ch >> 2;
        int k0 = (ch & 3) * 32;
        const f16* Ah = seg ? A2h : A1h;
        const f16* Al = seg ? A2l : A1l;
        const f16* Bh = seg ? B2h : B1h;
        const f16* Bl = seg ? B2l : B1l;
        uint32_t SB = smb + stage * STAGE_B;
        #pragma unroll
        for (int t = 0; t < 2; t++) {
            int m = (t == 0) ? lm : lm + 64;
            uint32_t dof = (t == 0) ? dof0 : dof1;
            int gm = row0 + m;
            uint32_t sz = (gm < N_NODES) ? 16u : 0u;
            size_t gmc = (gm < N_NODES) ? (size_t)gm : 0;
            CP16(SB + dof,           Ah + (gmc << 7) + k0 + lq * 8, sz);
            CP16(SB + TILE_AL + dof, Al + (gmc << 7) + k0 + lq * 8, sz);
            CP16(SB + TILE_WH + dof, Bh + ((size_t)m << 7) + k0 + lq * 8, 16u);
            CP16(SB + TILE_WL + dof, Bl + ((size_t)m << 7) + k0 + lq * 8, 16u);
        }
    };

    load_chunk(0, 0);
    CP_COMMIT();

    for (int ch = 0; ch < 8; ch++) {
        if (ch < 7) {
            load_chunk(ch + 1, (ch + 1) & 1);
            CP_COMMIT();
            CP_WAIT1();
        } else {
            CP_WAIT0();
        }
        __syncthreads();

        uint32_t SB = smb + (ch & 1) * STAGE_B;
        #pragma unroll
        for (int ks = 0; ks < 2; ks++) {
            uint32_t kso = (uint32_t)(ks * 32);
            uint32_t ah[2][4], al[2][4];
            #pragma unroll
            for (int mt = 0; mt < 2; mt++) {
                uint32_t abase = SB + (uint32_t)((warp_m * 32 + mt * 16) * TSTRIDE) + kso + aoff;
                LDSM4(ah[mt], abase);
                LDSM4(al[mt], abase + TILE_AL);
            }
            #pragma unroll
            for (int nt = 0; nt < 8; nt++) {
                uint32_t bbase = SB + TILE_WH + (uint32_t)((warp_n * 64 + nt * 8) * TSTRIDE) + kso + boff;
                uint32_t bh0, bh1, bl0, bl1;
                LDSM2(bh0, bh1, bbase);
                LDSM2(bl0, bl1, bbase + (TILE_WL - TILE_WH));
                #pragma unroll
                for (int mt = 0; mt < 2; mt++) {
                    mma_f16(c[mt][nt], ah[mt], bh0, bh1);
                    mma_f16(c[mt][nt], ah[mt], bl0, bl1);
                    mma_f16(c[mt][nt], al[mt], bh0, bh1);
                }
            }
        }
        __syncthreads();
    }

    int tg = lane & 3;
    int gp = lane >> 2;

    if (mode == 0) {
        // write fp16 hi/lo activations
        #pragma unroll
        for (int mt = 0; mt < 2; mt++) {
            int row = row0 + warp_m * 32 + mt * 16 + gp;
            #pragma unroll
            for (int nt = 0; nt < 8; nt++) {
                int col = warp_n * 64 + nt * 8 + 2 * tg;
                float b0 = bias[col], b1 = bias[col + 1];
                #pragma unroll
                for (int half = 0; half < 2; half++) {
                    int r = row + half * 8;
                    if (r < N_NODES) {
                        float v0 = fmaxf(c[mt][nt][half * 2 + 0] + b0, 0.f);
                        float v1 = fmaxf(c[mt][nt][half * 2 + 1] + b1, 0.f);
                        f16 h0, l0, h1, l1;
                        hsplit(v0, h0, l0); hsplit(v1, h1, l1);
                        f16 hh[2] = {h0, h1}, ll[2] = {l0, l1};
                        *(uint32_t*)(outh + (size_t)r * 128 + col) = *(const uint32_t*)hh;
                        *(uint32_t*)(outl + (size_t)r * 128 + col) = *(const uint32_t*)ll;
                    }
                }
            }
        }
    } else {
        // fused head: out[r, 0..3] = relu(h3[r,:]) @ Wh^T + bh
        float p[4][4];
        #pragma unroll
        for (int i = 0; i < 4; i++)
            #pragma unroll
            for (int o = 0; o < 4; o++) p[i][o] = 0.f;

        #pragma unroll
        for (int mt = 0; mt < 2; mt++) {
            #pragma unroll
            for (int nt = 0; nt < 8; nt++) {
                int col = warp_n * 64 + nt * 8 + 2 * tg;
                float b0 = bias[col], b1 = bias[col + 1];
                #pragma unroll
                for (int half = 0; half < 2; half++) {
                    float v0 = fmaxf(c[mt][nt][half * 2 + 0] + b0, 0.f);
                    float v1 = fmaxf(c[mt][nt][half * 2 + 1] + b1, 0.f);
                    #pragma unroll
                    for (int o = 0; o < 4; o++) {
                        p[mt * 2 + half][o] += v0 * Whd[o * 128 + col]
                                             + v1 * Whd[o * 128 + col + 1];
                    }
                }
            }
        }
        #pragma unroll
        for (int i = 0; i < 4; i++)
            #pragma unroll
            for (int o = 0; o < 4; o++) {
                float v = p[i][o];
                v += __shfl_xor_sync(0xffffffffu, v, 1);
                v += __shfl_xor_sync(0xffffffffu, v, 2);
                p[i][o] = v;
            }
        float* sred = (float*)sm;   // [128][8]: [row_local][warp_n*4 + o]
        if (tg == 0) {
            #pragma unroll
            for (int mt = 0; mt < 2; mt++)
                #pragma unroll
                for (int half = 0; half < 2; half++) {
                    int rl = warp_m * 32 + mt * 16 + half * 8 + gp;
                    #pragma unroll
                    for (int o = 0; o < 4; o++)
                        sred[rl * 8 + warp_n * 4 + o] = p[mt * 2 + half][o];
                }
        }
        __syncthreads();
        for (int t = tid; t < 512; t += 256) {
            int rl = t >> 2, o = t & 3;
            int r = row0 + rl;
            if (r < N_NODES)
                outd[(size_t)r * 4 + o] = sred[rl * 8 + o] + sred[rl * 8 + 4 + o] + bhd[o];
        }
    }
}

// ---------------- launch ----------------
extern "C" void kernel_launch(void* const* d_in, const int* in_sizes, int n_in,
                              void* d_out, int out_size)
{
    const float* x   = (const float*)d_in[0];
    const void*  ei  = d_in[1];
    const float* Wl1 = (const float*)d_in[2];
    const float* Wr1 = (const float*)d_in[3];
    const float* b1  = (const float*)d_in[4];
    const float* Wl2 = (const float*)d_in[5];
    const float* Wr2 = (const float*)d_in[6];
    const float* b2  = (const float*)d_in[7];
    const float* Wl3 = (const float*)d_in[8];
    const float* Wr3 = (const float*)d_in[9];
    const float* b3  = (const float*)d_in[10];
    const float* Wh  = (const float*)d_in[11];
    const float* bh  = (const float*)d_in[12];
    float* out = (float*)d_out;

    float *p_agg;
    f16 *p_aggh, *p_aggl, *p_h1h, *p_h1l, *p_h2h, *p_h2l, *p_Whs, *p_Wls;
    cudaGetSymbolAddress((void**)&p_agg,  g_agg);
    cudaGetSymbolAddress((void**)&p_aggh, g_aggh);
    cudaGetSymbolAddress((void**)&p_aggl, g_aggl);
    cudaGetSymbolAddress((void**)&p_h1h,  g_h1h);
    cudaGetSymbolAddress((void**)&p_h1l,  g_h1l);
    cudaGetSymbolAddress((void**)&p_h2h,  g_h2h);
    cudaGetSymbolAddress((void**)&p_h2l,  g_h2l);
    cudaGetSymbolAddress((void**)&p_Whs,  g_Wh);
    cudaGetSymbolAddress((void**)&p_Wls,  g_Wl);

    const int WB  = (N_NODES + 7) / 8;            // warp-per-node, 256 thr
    const int GB  = (N_NODES + 127) / 128;        // 391
    const int SB  = (N_NODES + 1023) / 1024;      // 49
    const int CB8 = (N_EDGES + 2047) / 2048;      // 293
    const int MSM = 2 * STAGE_B;                  // 81920

    cudaFuncSetAttribute(k_mma_gemm, cudaFuncAttributeMaxDynamicSharedMemorySize, MSM);

    // graph structure (+ W split inside k_count; g_deg/g_state zero invariant)
    k_count<<<CB8, 256>>>(ei, Wl2, Wr2, Wl3, Wr3);
    k_scan<<<SB, 1024>>>();
    k_fill<<<CB8, 256>>>(ei);

    const int HH = HIDDEN * HIDDEN;

    // layer 1 (FFMA, K=16) -> h1 hi/lo
    k_agg16<<<WB, 256>>>(x);
    k_sage_gemm<<<GB, 256>>>(p_agg, x, Wl1, Wr1, b1, p_h1h, p_h1l, IN_DIM);

    // layer 2 (fp16 split HMMA, pipelined) -> h2 hi/lo
    k_agg128<<<WB, 256>>>(p_h1h, p_aggh, p_aggl);
    k_mma_gemm<<<GB, 256, MSM>>>(p_aggh, p_aggl, p_h1h, p_h1l,
                                 p_Whs + 0 * HH, p_Wls + 0 * HH,
                                 p_Whs + 1 * HH, p_Wls + 1 * HH,
                                 b2, p_h2h, p_h2l, nullptr, nullptr, nullptr, 0);

    // layer 3 (fp16 split HMMA, pipelined) + fused head -> out
    k_agg128<<<WB, 256>>>(p_h2h, p_aggh, p_aggl);
    k_mma_gemm<<<GB, 256, MSM>>>(p_aggh, p_aggl, p_h2h, p_h2l,
                                 p_Whs + 2 * HH, p_Wls + 2 * HH,
                                 p_Whs + 3 * HH, p_Wls + 3 * HH,
                                 b3, nullptr, nullptr, Wh, bh, out, 1);
}